// round 5
// baseline (speedup 1.0000x reference)
#include <cuda_runtime.h>
#include <cuda_bf16.h>
#include <math.h>
#include <stdint.h>

// Problem constants
#define Bb    2
#define Ts    2048
#define Hq    32
#define Hkv   8
#define Dd    128
#define INNER 4096
#define KVIN  1024
#define MTOT  4096              // B*T
#define ATTN_SCALE 0.08838834764831845f

// ---------------------------------------------------------------------------
// Scratch (device globals)
// ---------------------------------------------------------------------------
__device__ float g_q[Bb*Ts*Hq*Dd];
__device__ float g_k[Bb*Ts*Hkv*Dd];
__device__ float g_v[Bb*Ts*Hkv*Dd];

// bf16 split-precision operands (raw u16)
__device__ unsigned short g_xh [MTOT*INNER],  g_xl [MTOT*INNER];
__device__ unsigned short g_wqh[INNER*INNER], g_wql[INNER*INNER];
__device__ unsigned short g_wkh[KVIN*INNER],  g_wkl[KVIN*INNER];
__device__ unsigned short g_wvh[KVIN*INNER],  g_wvl[KVIN*INNER];
__device__ unsigned short g_woh[INNER*INNER], g_wol[INNER*INNER];
__device__ unsigned short g_oh [MTOT*INNER],  g_ol [MTOT*INNER];

// attention operands
__device__ unsigned short g_qh2[Bb*Hq*Ts*Dd],  g_ql2[Bb*Hq*Ts*Dd];    // [b,h,t,d]
__device__ unsigned short g_kh2[Bb*Hkv*Ts*Dd], g_kl2[Bb*Hkv*Ts*Dd];   // [b,hkv,t,d]
__device__ unsigned short g_vth[Bb*Hkv*Ts*Dd], g_vtl[Bb*Hkv*Ts*Dd];   // [b,hkv,d,t]

// ---------------------------------------------------------------------------
// Helpers
// ---------------------------------------------------------------------------
__device__ __forceinline__ uint32_t smem_u32(const void* p) {
    uint32_t a;
    asm("{ .reg .u64 t; cvta.to.shared.u64 t, %1; cvt.u32.u64 %0, t; }"
        : "=r"(a) : "l"(p));
    return a;
}
#define CPA16(d,s) asm volatile("cp.async.cg.shared.global [%0], [%1], 16;" :: "r"(d), "l"(s))
#define CPC()      asm volatile("cp.async.commit_group;" ::: "memory")
#define CPW(n)     asm volatile("cp.async.wait_group %0;" :: "n"(n) : "memory")

__device__ __forceinline__ void ldsm4(uint32_t* r, uint32_t a) {
    asm volatile("ldmatrix.sync.aligned.m8n8.x4.shared.b16 {%0,%1,%2,%3}, [%4];"
        : "=r"(r[0]), "=r"(r[1]), "=r"(r[2]), "=r"(r[3]) : "r"(a));
}
__device__ __forceinline__ void mma16816(float* c, const uint32_t* a, const uint32_t* b) {
    asm volatile("mma.sync.aligned.m16n8k16.row.col.f32.bf16.bf16.f32 "
        "{%0,%1,%2,%3}, {%4,%5,%6,%7}, {%8,%9}, {%0,%1,%2,%3};"
        : "+f"(c[0]), "+f"(c[1]), "+f"(c[2]), "+f"(c[3])
        : "r"(a[0]), "r"(a[1]), "r"(a[2]), "r"(a[3]), "r"(b[0]), "r"(b[1]));
}

__device__ __forceinline__ unsigned short f2bf(float x) {
    __nv_bfloat16 h = __float2bfloat16(x);
    return *reinterpret_cast<unsigned short*>(&h);
}
__device__ __forceinline__ float bf2f(unsigned short u) {
    __nv_bfloat16 h = *reinterpret_cast<__nv_bfloat16*>(&u);
    return __bfloat162float(h);
}
__device__ __forceinline__ uint32_t pk2(float a, float b) {
    return (uint32_t)f2bf(a) | ((uint32_t)f2bf(b) << 16);
}
__device__ __forceinline__ uint32_t pk2lo(float a, float b) {
    return pk2(a - bf2f(f2bf(a)), b - bf2f(f2bf(b)));
}

// ---------------------------------------------------------------------------
// Conversion kernels
// ---------------------------------------------------------------------------
__global__ void split_kernel(const float* __restrict__ x,
                             unsigned short* __restrict__ h,
                             unsigned short* __restrict__ l, int n)
{
    int i = (blockIdx.x * 256 + threadIdx.x) * 4;
    if (i >= n) return;
    float4 v = *(const float4*)(x + i);
    unsigned short h0 = f2bf(v.x), h1 = f2bf(v.y), h2 = f2bf(v.z), h3 = f2bf(v.w);
    ushort4 hh; hh.x = h0; hh.y = h1; hh.z = h2; hh.w = h3;
    *(ushort4*)(h + i) = hh;
    ushort4 ll;
    ll.x = f2bf(v.x - bf2f(h0)); ll.y = f2bf(v.y - bf2f(h1));
    ll.z = f2bf(v.z - bf2f(h2)); ll.w = f2bf(v.w - bf2f(h3));
    *(ushort4*)(l + i) = ll;
}

// w[K,N] -> out[N,K] (transpose) + hi/lo split
__global__ void transpose_split(const float* __restrict__ w,
                                unsigned short* __restrict__ th,
                                unsigned short* __restrict__ tl, int K, int N)
{
    __shared__ float t[32][33];
    int n0 = blockIdx.x * 32, k0 = blockIdx.y * 32;
    #pragma unroll
    for (int i = 0; i < 32; i += 8)
        t[threadIdx.y + i][threadIdx.x] =
            w[(size_t)(k0 + threadIdx.y + i) * N + n0 + threadIdx.x];
    __syncthreads();
    #pragma unroll
    for (int i = 0; i < 32; i += 8) {
        float x = t[threadIdx.x][threadIdx.y + i];
        size_t o = (size_t)(n0 + threadIdx.y + i) * K + k0 + threadIdx.x;
        unsigned short hb = f2bf(x);
        th[o] = hb;
        tl[o] = f2bf(x - bf2f(hb));
    }
}

// Fused: RoPE (rotate-half) + bf16 hi/lo split + relayout (b,t,HH,d)->(b,HH,t,d)
__global__ void rope_split(const float* __restrict__ buf,
                           const float* __restrict__ cs,
                           const float* __restrict__ sn,
                           unsigned short* __restrict__ dh,
                           unsigned short* __restrict__ dl,
                           int HH, int nPairs)
{
    int idx = blockIdx.x * blockDim.x + threadIdx.x;
    if (idx >= nPairs) return;
    int d    = idx & 63;
    int rest = idx >> 6;              // (b*Ts + t)*HH + h
    int h    = rest % HH;
    int bt   = rest / HH;
    int t    = bt & (Ts - 1);
    int b    = bt >> 11;              // Ts = 2048
    size_t ib = (size_t)rest * 128;
    float l = buf[ib + d];
    float r = buf[ib + d + 64];
    float c0 = cs[t * 128 + d],      s0 = sn[t * 128 + d];
    float c1 = cs[t * 128 + d + 64], s1 = sn[t * 128 + d + 64];
    float f0 = l * c0 - r * s0;
    float f1 = r * c1 + l * s1;
    size_t ob = ((size_t)((b * HH + h) * Ts + t)) << 7;
    unsigned short h0 = f2bf(f0);
    dh[ob + d] = h0;
    dl[ob + d] = f2bf(f0 - bf2f(h0));
    unsigned short h1 = f2bf(f1);
    dh[ob + d + 64] = h1;
    dl[ob + d + 64] = f2bf(f1 - bf2f(h1));
}

// g_v (b,t,hkv,d) fp32 -> (b,hkv,d,t) bf16 hi/lo
__global__ void vtrans_split(const float* __restrict__ v,
                             unsigned short* __restrict__ th,
                             unsigned short* __restrict__ tl)
{
    __shared__ float s[32][33];
    int t0 = blockIdx.x * 32, d0 = blockIdx.y * 32;
    int b = blockIdx.z >> 3, hk = blockIdx.z & 7;
    int tx = threadIdx.x, ty = threadIdx.y;
    #pragma unroll
    for (int i = 0; i < 32; i += 8)
        s[ty + i][tx] = v[((size_t)(b * Ts + t0 + ty + i) * Hkv + hk) * Dd + d0 + tx];
    __syncthreads();
    #pragma unroll
    for (int i = 0; i < 32; i += 8) {
        float x = s[tx][ty + i];
        size_t o = ((size_t)((b * Hkv + hk) * Dd + d0 + ty + i)) * Ts + t0 + tx;
        unsigned short hb = f2bf(x);
        th[o] = hb;
        tl[o] = f2bf(x - bf2f(hb));
    }
}

// ---------------------------------------------------------------------------
// mma.sync split-bf16 GEMM: C[M,N] = A[M,K] @ Bt[N,K]^T  (3-term split)
// CTA 128x256, 8 warps (warp tile 64m x 64n), K chunk 32, 4-stage cp.async.
// smem/stage: Ah 8K | Al 8K | Bh 16K | Bl 16K = 48KB.
// Swizzle: 16B chunk c of row r at r*64 + ((c ^ ((r>>1)&3))<<4).
// ---------------------------------------------------------------------------
#define NSTG  4
#define STGB  49152
#define GSMEM (NSTG*STGB)

__global__ __launch_bounds__(256, 1) void gemm_mma(
    const unsigned short* __restrict__ Ah, const unsigned short* __restrict__ Al,
    const unsigned short* __restrict__ Bh, const unsigned short* __restrict__ Bl,
    float* __restrict__ C, int N, int K)
{
    extern __shared__ char smraw[];
    const uint32_t sb = smem_u32(smraw);
    const int tid  = threadIdx.x;
    const int wid  = tid >> 5;
    const int lane = tid & 31;
    const int mBase = blockIdx.y * 128;
    const int nBase = blockIdx.x * 256;
    const int warp_m = (wid & 1) * 64;
    const int warp_n = (wid >> 1) * 64;

    // ldmatrix stage-relative addresses (k-step 0)
    uint32_t aRel[4], bRel[4];
    {
        int r    = lane & 15;
        int half = lane >> 4;
        #pragma unroll
        for (int mt = 0; mt < 4; mt++) {
            int row = warp_m + mt * 16 + r;
            int sw  = (row >> 1) & 3;
            aRel[mt] = row * 64 + ((half ^ sw) << 4);
        }
        int nIn = (lane & 7) + ((lane >> 4) << 3);
        int cl  = (lane >> 3) & 1;
        #pragma unroll
        for (int bt = 0; bt < 4; bt++) {
            int row = warp_n + bt * 16 + nIn;
            int sw  = (row >> 1) & 3;
            bRel[bt] = 16384 + row * 64 + ((cl ^ sw) << 4);
        }
    }

    float cacc[4][8][4];
    #pragma unroll
    for (int a = 0; a < 4; a++)
        #pragma unroll
        for (int b = 0; b < 8; b++)
            #pragma unroll
            for (int c = 0; c < 4; c++) cacc[a][b][c] = 0.0f;

    const int NCH = K >> 5;

    auto load_chunk = [&](int st, int k0) {
        uint32_t base = sb + st * STGB;
        #pragma unroll
        for (int t = 0; t < 4; t++) {       // A: 128 rows x 4 chunks x 2 arrays
            int idx = tid + t * 256;
            int arr = idx >> 9, rem = idx & 511;
            int r = rem >> 2, c = rem & 3;
            uint32_t dst = base + arr * 8192 + r * 64 + ((c ^ ((r >> 1) & 3)) << 4);
            const unsigned short* src = (arr ? Al : Ah) +
                (size_t)(mBase + r) * K + k0 + c * 8;
            CPA16(dst, src);
        }
        #pragma unroll
        for (int t = 0; t < 8; t++) {       // B: 256 rows x 4 chunks x 2 arrays
            int idx = tid + t * 256;
            int arr = idx >> 10, rem = idx & 1023;
            int r = rem >> 2, c = rem & 3;
            uint32_t dst = base + 16384 + arr * 16384 + r * 64 + ((c ^ ((r >> 1) & 3)) << 4);
            const unsigned short* src = (arr ? Bl : Bh) +
                (size_t)(nBase + r) * K + k0 + c * 8;
            CPA16(dst, src);
        }
        CPC();
    };

    load_chunk(0, 0);
    load_chunk(1, 32);
    load_chunk(2, 64);

    for (int i = 0; i < NCH; i++) {
        CPW(2);
        __syncthreads();
        uint32_t base = sb + (uint32_t)(i & 3) * STGB;

        #pragma unroll
        for (int s = 0; s < 2; s++) {
            uint32_t sx = (uint32_t)(s << 5);
            uint32_t a_hi[4][4], a_lo[4][4];
            #pragma unroll
            for (int mt = 0; mt < 4; mt++) {
                uint32_t ad = base + (aRel[mt] ^ sx);
                ldsm4(a_hi[mt], ad);
                ldsm4(a_lo[mt], ad + 8192);
            }
            #pragma unroll
            for (int bt = 0; bt < 4; bt++) {
                uint32_t bd = base + (bRel[bt] ^ sx);
                uint32_t bh[4], bl[4];
                ldsm4(bh, bd);
                ldsm4(bl, bd + 16384);
                #pragma unroll
                for (int mt = 0; mt < 4; mt++) {
                    mma16816(cacc[mt][bt*2],   a_hi[mt], &bh[0]);
                    mma16816(cacc[mt][bt*2+1], a_hi[mt], &bh[2]);
                    mma16816(cacc[mt][bt*2],   a_hi[mt], &bl[0]);
                    mma16816(cacc[mt][bt*2+1], a_hi[mt], &bl[2]);
                    mma16816(cacc[mt][bt*2],   a_lo[mt], &bh[0]);
                    mma16816(cacc[mt][bt*2+1], a_lo[mt], &bh[2]);
                }
            }
        }
        __syncthreads();
        int nx = i + 3;
        if (nx < NCH) load_chunk(nx & 3, nx << 5);
        else          CPC();
    }

    // Epilogue
    const int rBase = mBase + warp_m + (lane >> 2);
    const int cBase = nBase + warp_n + (lane & 3) * 2;
    #pragma unroll
    for (int mt = 0; mt < 4; mt++) {
        #pragma unroll
        for (int nt = 0; nt < 8; nt++) {
            int r0 = rBase + mt * 16;
            int c0 = cBase + nt * 8;
            float2 v0 = make_float2(cacc[mt][nt][0], cacc[mt][nt][1]);
            float2 v1 = make_float2(cacc[mt][nt][2], cacc[mt][nt][3]);
            *(float2*)&C[(size_t)r0 * N + c0]       = v0;
            *(float2*)&C[(size_t)(r0 + 8) * N + c0] = v1;
        }
    }
}

// ---------------------------------------------------------------------------
// Tensor-core flash attention, split-bf16 (3-term), causal GQA.
// (unchanged from round 4 — verified correct)
// ---------------------------------------------------------------------------
#define AT_SMEM 196608

__global__ __launch_bounds__(256, 1) void attn_mma(
    const unsigned short* __restrict__ qh, const unsigned short* __restrict__ ql,
    const unsigned short* __restrict__ kh, const unsigned short* __restrict__ kl,
    const unsigned short* __restrict__ vh, const unsigned short* __restrict__ vl,
    unsigned short* __restrict__ oh, unsigned short* __restrict__ ol)
{
    extern __shared__ char smraw[];
    const uint32_t sb = smem_u32(smraw);
    const uint32_t QHs = sb;
    const uint32_t STs = sb + 65536;

    const int tid = threadIdx.x, wid = tid >> 5, lane = tid & 31;
    const int qb = blockIdx.x, h = blockIdx.y, b = blockIdx.z;
    const int hk = h >> 2;
    const int qBase = qb * 128;
    const int nT = qb * 2 + 2;

    const unsigned short* Qhg = qh + ((size_t)(b * Hq + h) * Ts + qBase) * Dd;
    const unsigned short* Qlg = ql + ((size_t)(b * Hq + h) * Ts + qBase) * Dd;
    const unsigned short* Khg = kh + (size_t)(b * Hkv + hk) * Ts * Dd;
    const unsigned short* Klg = kl + (size_t)(b * Hkv + hk) * Ts * Dd;
    const unsigned short* Vhg = vh + (size_t)(b * Hkv + hk) * Dd * Ts;
    const unsigned short* Vlg = vl + (size_t)(b * Hkv + hk) * Dd * Ts;

    #pragma unroll
    for (int t = 0; t < 16; t++) {
        int idx = tid + t * 256;
        int arr = idx >> 11, rem = idx & 2047;
        int r = rem >> 4, c = rem & 15;
        uint32_t dst = QHs + arr * 32768 + r * 256 + ((c ^ (r & 7)) << 4);
        const unsigned short* s = (arr ? Qlg : Qhg) + (size_t)r * Dd + c * 8;
        CPA16(dst, s);
    }

    auto load_tile = [&](int st, int kt) {
        uint32_t base = STs + st * 65536;
        #pragma unroll
        for (int t = 0; t < 8; t++) {
            int idx = tid + t * 256;
            int arr = idx >> 10, rem = idx & 1023;
            int r = rem >> 4, c = rem & 15;
            uint32_t dst = base + arr * 16384 + r * 256 + ((c ^ (r & 7)) << 4);
            const unsigned short* s = (arr ? Klg : Khg) +
                (size_t)(kt * 64 + r) * Dd + c * 8;
            CPA16(dst, s);
        }
        #pragma unroll
        for (int t = 0; t < 8; t++) {
            int idx = tid + t * 256;
            int arr = idx >> 10, rem = idx & 1023;
            int r = rem >> 3, c = rem & 7;
            uint32_t dst = base + 32768 + arr * 16384 + r * 128 + ((c ^ (r & 7)) << 4);
            const unsigned short* s = (arr ? Vlg : Vhg) +
                (size_t)r * Ts + kt * 64 + c * 8;
            CPA16(dst, s);
        }
    };

    load_tile(0, 0);
    CPC();

    const int qrow = wid * 16 + (lane & 15);
    const uint32_t qpb = (uint32_t)(qrow * 256 + (((lane >> 4) ^ (qrow & 1)) << 4));
    const uint32_t qpx = (uint32_t)((qrow & 6) << 4);
    const int nIn = (lane & 7) + ((lane >> 4) << 3);
    const int cl  = (lane >> 3) & 1;

    float m0 = -INFINITY, m1 = -INFINITY, l0 = 0.0f, l1 = 0.0f;
    float O[16][4];
    #pragma unroll
    for (int i = 0; i < 16; i++)
        #pragma unroll
        for (int j = 0; j < 4; j++) O[i][j] = 0.0f;

    const int rA = qBase + wid * 16 + (lane >> 2);
    const int rB = rA + 8;

    for (int kt = 0; kt < nT; kt++) {
        if (kt + 1 < nT) { load_tile((kt + 1) & 1, kt + 1); CPC(); CPW(1); }
        else            { CPW(0); }
        __syncthreads();
        const uint32_t KB = STs + (kt & 1) * 65536;
        const uint32_t VB = KB + 32768;

        float S[8][4];
        #pragma unroll
        for (int i = 0; i < 8; i++)
            #pragma unroll
            for (int j = 0; j < 4; j++) S[i][j] = 0.0f;

        #pragma unroll
        for (int ks = 0; ks < 8; ks++) {
            uint32_t qa = QHs + qpb + (((uint32_t)ks << 5) ^ qpx);
            uint32_t ah[4], al[4];
            ldsm4(ah, qa);
            ldsm4(al, qa + 32768);
            #pragma unroll
            for (int np = 0; np < 4; np++) {
                int krow = np * 16 + nIn;
                uint32_t ka = KB + krow * 256 + ((uint32_t)((cl ^ (krow & 1)) << 4))
                            + (((uint32_t)ks << 5) ^ ((uint32_t)(krow & 6) << 4));
                uint32_t bh[4], bl[4];
                ldsm4(bh, ka);
                ldsm4(bl, ka + 16384);
                mma16816(S[2*np],   ah, &bh[0]);
                mma16816(S[2*np+1], ah, &bh[2]);
                mma16816(S[2*np],   ah, &bl[0]);
                mma16816(S[2*np+1], ah, &bl[2]);
                mma16816(S[2*np],   al, &bh[0]);
                mma16816(S[2*np+1], al, &bh[2]);
            }
        }

        if (kt >= 2 * qb) {
            #pragma unroll
            for (int nt = 0; nt < 8; nt++) {
                int jg = kt * 64 + nt * 8 + (lane & 3) * 2;
                S[nt][0] = (jg     <= rA) ? S[nt][0] * ATTN_SCALE : -30000.0f;
                S[nt][1] = (jg + 1 <= rA) ? S[nt][1] * ATTN_SCALE : -30000.0f;
                S[nt][2] = (jg     <= rB) ? S[nt][2] * ATTN_SCALE : -30000.0f;
                S[nt][3] = (jg + 1 <= rB) ? S[nt][3] * ATTN_SCALE : -30000.0f;
            }
        } else {
            #pragma unroll
            for (int nt = 0; nt < 8; nt++) {
                S[nt][0] *= ATTN_SCALE; S[nt][1] *= ATTN_SCALE;
                S[nt][2] *= ATTN_SCALE; S[nt][3] *= ATTN_SCALE;
            }
        }

        float bm0 = -INFINITY, bm1 = -INFINITY;
        #pragma unroll
        for (int nt = 0; nt < 8; nt++) {
            bm0 = fmaxf(bm0, fmaxf(S[nt][0], S[nt][1]));
            bm1 = fmaxf(bm1, fmaxf(S[nt][2], S[nt][3]));
        }
        bm0 = fmaxf(bm0, __shfl_xor_sync(0xffffffffu, bm0, 1));
        bm0 = fmaxf(bm0, __shfl_xor_sync(0xffffffffu, bm0, 2));
        bm1 = fmaxf(bm1, __shfl_xor_sync(0xffffffffu, bm1, 1));
        bm1 = fmaxf(bm1, __shfl_xor_sync(0xffffffffu, bm1, 2));
        float mn0 = fmaxf(m0, bm0);
        float mn1 = fmaxf(m1, bm1);

        float bs0 = 0.0f, bs1 = 0.0f;
        #pragma unroll
        for (int nt = 0; nt < 8; nt++) {
            S[nt][0] = __expf(S[nt][0] - mn0); bs0 += S[nt][0];
            S[nt][1] = __expf(S[nt][1] - mn0); bs0 += S[nt][1];
            S[nt][2] = __expf(S[nt][2] - mn1); bs1 += S[nt][2];
            S[nt][3] = __expf(S[nt][3] - mn1); bs1 += S[nt][3];
        }
        bs0 += __shfl_xor_sync(0xffffffffu, bs0, 1);
        bs0 += __shfl_xor_sync(0xffffffffu, bs0, 2);
        bs1 += __shfl_xor_sync(0xffffffffu, bs1, 1);
        bs1 += __shfl_xor_sync(0xffffffffu, bs1, 2);

        float a0 = __expf(m0 - mn0);
        float a1 = __expf(m1 - mn1);
        l0 = l0 * a0 + bs0;
        l1 = l1 * a1 + bs1;
        m0 = mn0; m1 = mn1;
        #pragma unroll
        for (int dt = 0; dt < 16; dt++) {
            O[dt][0] *= a0; O[dt][1] *= a0;
            O[dt][2] *= a1; O[dt][3] *= a1;
        }

        #pragma unroll
        for (int j = 0; j < 4; j++) {
            uint32_t pah[4], pal[4];
            pah[0] = pk2  (S[2*j][0],   S[2*j][1]);
            pah[1] = pk2  (S[2*j][2],   S[2*j][3]);
            pah[2] = pk2  (S[2*j+1][0], S[2*j+1][1]);
            pah[3] = pk2  (S[2*j+1][2], S[2*j+1][3]);
            pal[0] = pk2lo(S[2*j][0],   S[2*j][1]);
            pal[1] = pk2lo(S[2*j][2],   S[2*j][3]);
            pal[2] = pk2lo(S[2*j+1][0], S[2*j+1][1]);
            pal[3] = pk2lo(S[2*j+1][2], S[2*j+1][3]);
            #pragma unroll
            for (int dp = 0; dp < 8; dp++) {
                int vrow = dp * 16 + nIn;
                uint32_t va = VB + vrow * 128 + ((uint32_t)((cl ^ (vrow & 1)) << 4))
                            + (((uint32_t)j << 5) ^ ((uint32_t)(vrow & 6) << 4));
                uint32_t bh[4], bl[4];
                ldsm4(bh, va);
                ldsm4(bl, va + 16384);
                mma16816(O[2*dp],   pah, &bh[0]);
                mma16816(O[2*dp+1], pah, &bh[2]);
                mma16816(O[2*dp],   pah, &bl[0]);
                mma16816(O[2*dp+1], pah, &bl[2]);
                mma16816(O[2*dp],   pal, &bh[0]);
                mma16816(O[2*dp+1], pal, &bh[2]);
            }
        }
        __syncthreads();
    }

    float inv0 = 1.0f / l0;
    float inv1 = 1.0f / l1;
    size_t rowA = ((size_t)(b * Ts + rA)) * INNER + h * Dd;
    size_t rowB = ((size_t)(b * Ts + rB)) * INNER + h * Dd;
    #pragma unroll
    for (int dt = 0; dt < 16; dt++) {
        int col = dt * 8 + (lane & 3) * 2;
        float x0 = O[dt][0] * inv0, x1 = O[dt][1] * inv0;
        float y0 = O[dt][2] * inv1, y1 = O[dt][3] * inv1;
        *(uint32_t*)&oh[rowA + col] = pk2(x0, x1);
        *(uint32_t*)&ol[rowA + col] = pk2lo(x0, x1);
        *(uint32_t*)&oh[rowB + col] = pk2(y0, y1);
        *(uint32_t*)&ol[rowB + col] = pk2lo(y0, y1);
    }
}

// ---------------------------------------------------------------------------
// Launch
// ---------------------------------------------------------------------------
extern "C" void kernel_launch(void* const* d_in, const int* in_sizes, int n_in,
                              void* d_out, int out_size)
{
    const float* stm  = (const float*)d_in[0];
    const float* wq   = (const float*)d_in[1];
    const float* wk   = (const float*)d_in[2];
    const float* wv   = (const float*)d_in[3];
    const float* wo   = (const float*)d_in[4];
    const float* cosv = (const float*)d_in[5];
    const float* sinv = (const float*)d_in[6];
    float* out = (float*)d_out;

    float *q, *k, *v;
    cudaGetSymbolAddress((void**)&q, g_q);
    cudaGetSymbolAddress((void**)&k, g_k);
    cudaGetSymbolAddress((void**)&v, g_v);
    unsigned short *xh, *xl, *wqh, *wql, *wkh, *wkl, *wvh, *wvl, *woh, *wol, *oh, *ol;
    cudaGetSymbolAddress((void**)&xh,  g_xh);  cudaGetSymbolAddress((void**)&xl,  g_xl);
    cudaGetSymbolAddress((void**)&wqh, g_wqh); cudaGetSymbolAddress((void**)&wql, g_wql);
    cudaGetSymbolAddress((void**)&wkh, g_wkh); cudaGetSymbolAddress((void**)&wkl, g_wkl);
    cudaGetSymbolAddress((void**)&wvh, g_wvh); cudaGetSymbolAddress((void**)&wvl, g_wvl);
    cudaGetSymbolAddress((void**)&woh, g_woh); cudaGetSymbolAddress((void**)&wol, g_wol);
    cudaGetSymbolAddress((void**)&oh,  g_oh);  cudaGetSymbolAddress((void**)&ol,  g_ol);
    unsigned short *qh2, *ql2, *kh2, *kl2, *vth, *vtl;
    cudaGetSymbolAddress((void**)&qh2, g_qh2); cudaGetSymbolAddress((void**)&ql2, g_ql2);
    cudaGetSymbolAddress((void**)&kh2, g_kh2); cudaGetSymbolAddress((void**)&kl2, g_kl2);
    cudaGetSymbolAddress((void**)&vth, g_vth); cudaGetSymbolAddress((void**)&vtl, g_vtl);

    cudaFuncSetAttribute(gemm_mma, cudaFuncAttributeMaxDynamicSharedMemorySize, GSMEM);
    cudaFuncSetAttribute(attn_mma, cudaFuncAttributeMaxDynamicSharedMemorySize, AT_SMEM);

    // Conversions
    split_kernel<<<MTOT*INNER/1024, 256>>>(stm, xh, xl, MTOT*INNER);
    transpose_split<<<dim3(INNER/32, INNER/32), dim3(32,8)>>>(wq, wqh, wql, INNER, INNER);
    transpose_split<<<dim3(KVIN/32,  INNER/32), dim3(32,8)>>>(wk, wkh, wkl, INNER, KVIN);
    transpose_split<<<dim3(KVIN/32,  INNER/32), dim3(32,8)>>>(wv, wvh, wvl, INNER, KVIN);
    transpose_split<<<dim3(INNER/32, INNER/32), dim3(32,8)>>>(wo, woh, wol, INNER, INNER);

    // QKV projections (128x256 tiles)
    gemm_mma<<<dim3(INNER/256, MTOT/128), 256, GSMEM>>>(xh, xl, wqh, wql, q, INNER, INNER);
    gemm_mma<<<dim3(KVIN/256,  MTOT/128), 256, GSMEM>>>(xh, xl, wkh, wkl, k, KVIN,  INNER);
    gemm_mma<<<dim3(KVIN/256,  MTOT/128), 256, GSMEM>>>(xh, xl, wvh, wvl, v, KVIN,  INNER);

    // Fused RoPE + split + relayout for q, k; transpose+split for v
    {
        int nq = Bb * Ts * Hq  * 64;
        int nk = Bb * Ts * Hkv * 64;
        rope_split<<<(nq + 255) / 256, 256>>>(q, cosv, sinv, qh2, ql2, Hq,  nq);
        rope_split<<<(nk + 255) / 256, 256>>>(k, cosv, sinv, kh2, kl2, Hkv, nk);
    }
    vtrans_split<<<dim3(Ts/32, Dd/32, Bb*Hkv), dim3(32,8)>>>(v, vth, vtl);

    // Tensor-core attention (writes bf16 hi/lo directly)
    attn_mma<<<dim3(Ts/128, Hq, Bb), 256, AT_SMEM>>>(qh2, ql2, kh2, kl2, vth, vtl, oh, ol);

    // Output projection
    gemm_mma<<<dim3(INNER/256, MTOT/128), 256, GSMEM>>>(oh, ol, woh, wol, out, INNER, INNER);
}

// round 6
// speedup vs baseline: 1.0166x; 1.0166x over previous
#include <cuda_runtime.h>
#include <cuda_bf16.h>
#include <math.h>
#include <stdint.h>

// Problem constants
#define Bb    2
#define Ts    2048
#define Hq    32
#define Hkv   8
#define Dd    128
#define INNER 4096
#define KVIN  1024
#define MTOT  4096              // B*T
#define ATTN_SCALE 0.08838834764831845f

// ---------------------------------------------------------------------------
// Scratch (device globals)
// ---------------------------------------------------------------------------
__device__ float g_q[Bb*Ts*Hq*Dd];
__device__ float g_k[Bb*Ts*Hkv*Dd];
__device__ float g_v[Bb*Ts*Hkv*Dd];

// bf16 split-precision operands (raw u16)
__device__ unsigned short g_xh [MTOT*INNER],  g_xl [MTOT*INNER];
__device__ unsigned short g_wqh[INNER*INNER], g_wql[INNER*INNER];
__device__ unsigned short g_wkh[KVIN*INNER],  g_wkl[KVIN*INNER];
__device__ unsigned short g_wvh[KVIN*INNER],  g_wvl[KVIN*INNER];
__device__ unsigned short g_woh[INNER*INNER], g_wol[INNER*INNER];
__device__ unsigned short g_oh [MTOT*INNER],  g_ol [MTOT*INNER];

// attention operands
__device__ unsigned short g_qh2[Bb*Hq*Ts*Dd],  g_ql2[Bb*Hq*Ts*Dd];    // [b,h,t,d]
__device__ unsigned short g_kh2[Bb*Hkv*Ts*Dd], g_kl2[Bb*Hkv*Ts*Dd];   // [b,hkv,t,d]
__device__ unsigned short g_vth[Bb*Hkv*Ts*Dd], g_vtl[Bb*Hkv*Ts*Dd];   // [b,hkv,d,t]

// ---------------------------------------------------------------------------
// Helpers
// ---------------------------------------------------------------------------
__device__ __forceinline__ uint32_t smem_u32(const void* p) {
    uint32_t a;
    asm("{ .reg .u64 t; cvta.to.shared.u64 t, %1; cvt.u32.u64 %0, t; }"
        : "=r"(a) : "l"(p));
    return a;
}
#define CPA16(d,s) asm volatile("cp.async.cg.shared.global [%0], [%1], 16;" :: "r"(d), "l"(s))
#define CPC()      asm volatile("cp.async.commit_group;" ::: "memory")
#define CPW(n)     asm volatile("cp.async.wait_group %0;" :: "n"(n) : "memory")

__device__ __forceinline__ void ldsm4(uint32_t* r, uint32_t a) {
    asm volatile("ldmatrix.sync.aligned.m8n8.x4.shared.b16 {%0,%1,%2,%3}, [%4];"
        : "=r"(r[0]), "=r"(r[1]), "=r"(r[2]), "=r"(r[3]) : "r"(a));
}
__device__ __forceinline__ void mma16816(float* c, const uint32_t* a, const uint32_t* b) {
    asm volatile("mma.sync.aligned.m16n8k16.row.col.f32.bf16.bf16.f32 "
        "{%0,%1,%2,%3}, {%4,%5,%6,%7}, {%8,%9}, {%0,%1,%2,%3};"
        : "+f"(c[0]), "+f"(c[1]), "+f"(c[2]), "+f"(c[3])
        : "r"(a[0]), "r"(a[1]), "r"(a[2]), "r"(a[3]), "r"(b[0]), "r"(b[1]));
}

__device__ __forceinline__ unsigned short f2bf(float x) {
    __nv_bfloat16 h = __float2bfloat16(x);
    return *reinterpret_cast<unsigned short*>(&h);
}
__device__ __forceinline__ float bf2f(unsigned short u) {
    __nv_bfloat16 h = *reinterpret_cast<__nv_bfloat16*>(&u);
    return __bfloat162float(h);
}
__device__ __forceinline__ uint32_t pk2(float a, float b) {
    return (uint32_t)f2bf(a) | ((uint32_t)f2bf(b) << 16);
}
__device__ __forceinline__ uint32_t pk2lo(float a, float b) {
    return pk2(a - bf2f(f2bf(a)), b - bf2f(f2bf(b)));
}

// ---------------------------------------------------------------------------
// Conversion kernels
// ---------------------------------------------------------------------------
__global__ void split_kernel(const float* __restrict__ x,
                             unsigned short* __restrict__ h,
                             unsigned short* __restrict__ l, int n)
{
    int i = (blockIdx.x * 256 + threadIdx.x) * 4;
    if (i >= n) return;
    float4 v = *(const float4*)(x + i);
    unsigned short h0 = f2bf(v.x), h1 = f2bf(v.y), h2 = f2bf(v.z), h3 = f2bf(v.w);
    ushort4 hh; hh.x = h0; hh.y = h1; hh.z = h2; hh.w = h3;
    *(ushort4*)(h + i) = hh;
    ushort4 ll;
    ll.x = f2bf(v.x - bf2f(h0)); ll.y = f2bf(v.y - bf2f(h1));
    ll.z = f2bf(v.z - bf2f(h2)); ll.w = f2bf(v.w - bf2f(h3));
    *(ushort4*)(l + i) = ll;
}

// w[K,N] -> out[N,K] (transpose) + hi/lo split
__global__ void transpose_split(const float* __restrict__ w,
                                unsigned short* __restrict__ th,
                                unsigned short* __restrict__ tl, int K, int N)
{
    __shared__ float t[32][33];
    int n0 = blockIdx.x * 32, k0 = blockIdx.y * 32;
    #pragma unroll
    for (int i = 0; i < 32; i += 8)
        t[threadIdx.y + i][threadIdx.x] =
            w[(size_t)(k0 + threadIdx.y + i) * N + n0 + threadIdx.x];
    __syncthreads();
    #pragma unroll
    for (int i = 0; i < 32; i += 8) {
        float x = t[threadIdx.x][threadIdx.y + i];
        size_t o = (size_t)(n0 + threadIdx.y + i) * K + k0 + threadIdx.x;
        unsigned short hb = f2bf(x);
        th[o] = hb;
        tl[o] = f2bf(x - bf2f(hb));
    }
}

// Fused: RoPE (rotate-half) + bf16 hi/lo split + relayout (b,t,HH,d)->(b,HH,t,d)
__global__ void rope_split(const float* __restrict__ buf,
                           const float* __restrict__ cs,
                           const float* __restrict__ sn,
                           unsigned short* __restrict__ dh,
                           unsigned short* __restrict__ dl,
                           int HH, int nPairs)
{
    int idx = blockIdx.x * blockDim.x + threadIdx.x;
    if (idx >= nPairs) return;
    int d    = idx & 63;
    int rest = idx >> 6;              // (b*Ts + t)*HH + h
    int h    = rest % HH;
    int bt   = rest / HH;
    int t    = bt & (Ts - 1);
    int b    = bt >> 11;              // Ts = 2048
    size_t ib = (size_t)rest * 128;
    float l = buf[ib + d];
    float r = buf[ib + d + 64];
    float c0 = cs[t * 128 + d],      s0 = sn[t * 128 + d];
    float c1 = cs[t * 128 + d + 64], s1 = sn[t * 128 + d + 64];
    float f0 = l * c0 - r * s0;
    float f1 = r * c1 + l * s1;
    size_t ob = ((size_t)((b * HH + h) * Ts + t)) << 7;
    unsigned short h0 = f2bf(f0);
    dh[ob + d] = h0;
    dl[ob + d] = f2bf(f0 - bf2f(h0));
    unsigned short h1 = f2bf(f1);
    dh[ob + d + 64] = h1;
    dl[ob + d + 64] = f2bf(f1 - bf2f(h1));
}

// g_v (b,t,hkv,d) fp32 -> (b,hkv,d,t) bf16 hi/lo
__global__ void vtrans_split(const float* __restrict__ v,
                             unsigned short* __restrict__ th,
                             unsigned short* __restrict__ tl)
{
    __shared__ float s[32][33];
    int t0 = blockIdx.x * 32, d0 = blockIdx.y * 32;
    int b = blockIdx.z >> 3, hk = blockIdx.z & 7;
    int tx = threadIdx.x, ty = threadIdx.y;
    #pragma unroll
    for (int i = 0; i < 32; i += 8)
        s[ty + i][tx] = v[((size_t)(b * Ts + t0 + ty + i) * Hkv + hk) * Dd + d0 + tx];
    __syncthreads();
    #pragma unroll
    for (int i = 0; i < 32; i += 8) {
        float x = s[tx][ty + i];
        size_t o = ((size_t)((b * Hkv + hk) * Dd + d0 + ty + i)) * Ts + t0 + tx;
        unsigned short hb = f2bf(x);
        th[o] = hb;
        tl[o] = f2bf(x - bf2f(hb));
    }
}

// ---------------------------------------------------------------------------
// mma.sync split-bf16 GEMM: C[M,N] = A[M,K] @ Bt[N,K]^T  (3-term split)
// CTA 128x128, 8 warps (warp tile 64m x 32n), K chunk 32, 4-stage cp.async.
// smem/stage: Ah 8K | Al 8K | Bh 8K | Bl 8K = 32KB.
// Swizzle: 16B chunk c of row r at r*64 + ((c ^ ((r>>1)&3))<<4).
// (round-4 verified config)
// ---------------------------------------------------------------------------
#define NSTG  4
#define STGB  32768
#define GSMEM (NSTG*STGB)

__global__ __launch_bounds__(256, 1) void gemm_mma(
    const unsigned short* __restrict__ Ah, const unsigned short* __restrict__ Al,
    const unsigned short* __restrict__ Bh, const unsigned short* __restrict__ Bl,
    float* __restrict__ C, int N, int K)
{
    extern __shared__ char smraw[];
    const uint32_t sb = smem_u32(smraw);
    const int tid  = threadIdx.x;
    const int wid  = tid >> 5;
    const int lane = tid & 31;
    const int mBase = blockIdx.y * 128;
    const int nBase = blockIdx.x * 128;
    const int warp_m = (wid & 1) * 64;
    const int warp_n = (wid >> 1) * 32;

    uint32_t aAddr[4], bAddr[2];
    {
        int r    = lane & 15;
        int half = lane >> 4;
        #pragma unroll
        for (int mt = 0; mt < 4; mt++) {
            int row = warp_m + mt * 16 + r;
            int sw  = (row >> 1) & 3;
            aAddr[mt] = sb + row * 64 + ((half ^ sw) << 4);
        }
        int nIn = (lane & 7) + (lane >> 4) * 8;
        int cl  = (lane >> 3) & 1;
        #pragma unroll
        for (int bt = 0; bt < 2; bt++) {
            int row = warp_n + bt * 16 + nIn;
            int sw  = (row >> 1) & 3;
            bAddr[bt] = sb + 16384 + row * 64 + ((cl ^ sw) << 4);
        }
    }

    const int ldRow = tid >> 2;
    const int ldC   = tid & 3;

    float cacc[4][4][4];
    #pragma unroll
    for (int a = 0; a < 4; a++)
        #pragma unroll
        for (int b = 0; b < 4; b++)
            #pragma unroll
            for (int c = 0; c < 4; c++) cacc[a][b][c] = 0.0f;

    const int NCH = K >> 5;

    auto load_chunk = [&](int st, int k0) {
        #pragma unroll
        for (int h = 0; h < 2; h++) {
            int row = ldRow + h * 64;
            int sw  = (row >> 1) & 3;
            uint32_t so = sb + st * STGB + row * 64 + ((ldC ^ sw) << 4);
            size_t ga = (size_t)(mBase + row) * K + k0 + ldC * 8;
            CPA16(so,         Ah + ga);
            CPA16(so + 8192,  Al + ga);
            size_t gb = (size_t)(nBase + row) * K + k0 + ldC * 8;
            CPA16(so + 16384, Bh + gb);
            CPA16(so + 24576, Bl + gb);
        }
        CPC();
    };

    load_chunk(0, 0);
    load_chunk(1, 32);
    load_chunk(2, 64);

    for (int i = 0; i < NCH; i++) {
        CPW(2);
        __syncthreads();
        uint32_t stOff = (uint32_t)(i & 3) * STGB;

        #pragma unroll
        for (int s = 0; s < 2; s++) {
            uint32_t sx = (uint32_t)(s << 5);
            uint32_t a_hi[4][4], a_lo[4][4], b_hi[2][4], b_lo[2][4];
            #pragma unroll
            for (int mt = 0; mt < 4; mt++) {
                uint32_t ad = (aAddr[mt] ^ sx) + stOff;
                ldsm4(a_hi[mt], ad);
                ldsm4(a_lo[mt], ad + 8192);
            }
            #pragma unroll
            for (int bt = 0; bt < 2; bt++) {
                uint32_t bd = (bAddr[bt] ^ sx) + stOff;
                ldsm4(b_hi[bt], bd);
                ldsm4(b_lo[bt], bd + 8192);
            }
            #pragma unroll
            for (int mt = 0; mt < 4; mt++) {
                #pragma unroll
                for (int bt = 0; bt < 2; bt++) {
                    mma16816(cacc[mt][bt*2],   a_hi[mt], &b_hi[bt][0]);
                    mma16816(cacc[mt][bt*2+1], a_hi[mt], &b_hi[bt][2]);
                    mma16816(cacc[mt][bt*2],   a_hi[mt], &b_lo[bt][0]);
                    mma16816(cacc[mt][bt*2+1], a_hi[mt], &b_lo[bt][2]);
                    mma16816(cacc[mt][bt*2],   a_lo[mt], &b_hi[bt][0]);
                    mma16816(cacc[mt][bt*2+1], a_lo[mt], &b_hi[bt][2]);
                }
            }
        }
        __syncthreads();
        int nx = i + 3;
        if (nx < NCH) load_chunk(nx & 3, nx << 5);
        else          CPC();
    }

    const int rBase = mBase + warp_m + (lane >> 2);
    const int cBase = nBase + warp_n + (lane & 3) * 2;
    #pragma unroll
    for (int mt = 0; mt < 4; mt++) {
        #pragma unroll
        for (int nt = 0; nt < 4; nt++) {
            int r0 = rBase + mt * 16;
            int c0 = cBase + nt * 8;
            float2 v0 = make_float2(cacc[mt][nt][0], cacc[mt][nt][1]);
            float2 v1 = make_float2(cacc[mt][nt][2], cacc[mt][nt][3]);
            *(float2*)&C[(size_t)r0 * N + c0]       = v0;
            *(float2*)&C[(size_t)(r0 + 8) * N + c0] = v1;
        }
    }
}

// ---------------------------------------------------------------------------
// Tensor-core flash attention, split-bf16 (3-term), causal GQA.
// ---------------------------------------------------------------------------
#define AT_SMEM 196608

__global__ __launch_bounds__(256, 1) void attn_mma(
    const unsigned short* __restrict__ qh, const unsigned short* __restrict__ ql,
    const unsigned short* __restrict__ kh, const unsigned short* __restrict__ kl,
    const unsigned short* __restrict__ vh, const unsigned short* __restrict__ vl,
    unsigned short* __restrict__ oh, unsigned short* __restrict__ ol)
{
    extern __shared__ char smraw[];
    const uint32_t sb = smem_u32(smraw);
    const uint32_t QHs = sb;
    const uint32_t STs = sb + 65536;

    const int tid = threadIdx.x, wid = tid >> 5, lane = tid & 31;
    const int qb = blockIdx.x, h = blockIdx.y, b = blockIdx.z;
    const int hk = h >> 2;
    const int qBase = qb * 128;
    const int nT = qb * 2 + 2;

    const unsigned short* Qhg = qh + ((size_t)(b * Hq + h) * Ts + qBase) * Dd;
    const unsigned short* Qlg = ql + ((size_t)(b * Hq + h) * Ts + qBase) * Dd;
    const unsigned short* Khg = kh + (size_t)(b * Hkv + hk) * Ts * Dd;
    const unsigned short* Klg = kl + (size_t)(b * Hkv + hk) * Ts * Dd;
    const unsigned short* Vhg = vh + (size_t)(b * Hkv + hk) * Dd * Ts;
    const unsigned short* Vlg = vl + (size_t)(b * Hkv + hk) * Dd * Ts;

    #pragma unroll
    for (int t = 0; t < 16; t++) {
        int idx = tid + t * 256;
        int arr = idx >> 11, rem = idx & 2047;
        int r = rem >> 4, c = rem & 15;
        uint32_t dst = QHs + arr * 32768 + r * 256 + ((c ^ (r & 7)) << 4);
        const unsigned short* s = (arr ? Qlg : Qhg) + (size_t)r * Dd + c * 8;
        CPA16(dst, s);
    }

    auto load_tile = [&](int st, int kt) {
        uint32_t base = STs + st * 65536;
        #pragma unroll
        for (int t = 0; t < 8; t++) {
            int idx = tid + t * 256;
            int arr = idx >> 10, rem = idx & 1023;
            int r = rem >> 4, c = rem & 15;
            uint32_t dst = base + arr * 16384 + r * 256 + ((c ^ (r & 7)) << 4);
            const unsigned short* s = (arr ? Klg : Khg) +
                (size_t)(kt * 64 + r) * Dd + c * 8;
            CPA16(dst, s);
        }
        #pragma unroll
        for (int t = 0; t < 8; t++) {
            int idx = tid + t * 256;
            int arr = idx >> 10, rem = idx & 1023;
            int r = rem >> 3, c = rem & 7;
            uint32_t dst = base + 32768 + arr * 16384 + r * 128 + ((c ^ (r & 7)) << 4);
            const unsigned short* s = (arr ? Vlg : Vhg) +
                (size_t)r * Ts + kt * 64 + c * 8;
            CPA16(dst, s);
        }
    };

    load_tile(0, 0);
    CPC();

    const int qrow = wid * 16 + (lane & 15);
    const uint32_t qpb = (uint32_t)(qrow * 256 + (((lane >> 4) ^ (qrow & 1)) << 4));
    const uint32_t qpx = (uint32_t)((qrow & 6) << 4);
    const int nIn = (lane & 7) + ((lane >> 4) << 3);
    const int cl  = (lane >> 3) & 1;

    float m0 = -INFINITY, m1 = -INFINITY, l0 = 0.0f, l1 = 0.0f;
    float O[16][4];
    #pragma unroll
    for (int i = 0; i < 16; i++)
        #pragma unroll
        for (int j = 0; j < 4; j++) O[i][j] = 0.0f;

    const int rA = qBase + wid * 16 + (lane >> 2);
    const int rB = rA + 8;

    for (int kt = 0; kt < nT; kt++) {
        if (kt + 1 < nT) { load_tile((kt + 1) & 1, kt + 1); CPC(); CPW(1); }
        else            { CPW(0); }
        __syncthreads();
        const uint32_t KB = STs + (kt & 1) * 65536;
        const uint32_t VB = KB + 32768;

        float S[8][4];
        #pragma unroll
        for (int i = 0; i < 8; i++)
            #pragma unroll
            for (int j = 0; j < 4; j++) S[i][j] = 0.0f;

        #pragma unroll
        for (int ks = 0; ks < 8; ks++) {
            uint32_t qa = QHs + qpb + (((uint32_t)ks << 5) ^ qpx);
            uint32_t ah[4], al[4];
            ldsm4(ah, qa);
            ldsm4(al, qa + 32768);
            #pragma unroll
            for (int np = 0; np < 4; np++) {
                int krow = np * 16 + nIn;
                uint32_t ka = KB + krow * 256 + ((uint32_t)((cl ^ (krow & 1)) << 4))
                            + (((uint32_t)ks << 5) ^ ((uint32_t)(krow & 6) << 4));
                uint32_t bh[4], bl[4];
                ldsm4(bh, ka);
                ldsm4(bl, ka + 16384);
                mma16816(S[2*np],   ah, &bh[0]);
                mma16816(S[2*np+1], ah, &bh[2]);
                mma16816(S[2*np],   ah, &bl[0]);
                mma16816(S[2*np+1], ah, &bl[2]);
                mma16816(S[2*np],   al, &bh[0]);
                mma16816(S[2*np+1], al, &bh[2]);
            }
        }

        if (kt >= 2 * qb) {
            #pragma unroll
            for (int nt = 0; nt < 8; nt++) {
                int jg = kt * 64 + nt * 8 + (lane & 3) * 2;
                S[nt][0] = (jg     <= rA) ? S[nt][0] * ATTN_SCALE : -30000.0f;
                S[nt][1] = (jg + 1 <= rA) ? S[nt][1] * ATTN_SCALE : -30000.0f;
                S[nt][2] = (jg     <= rB) ? S[nt][2] * ATTN_SCALE : -30000.0f;
                S[nt][3] = (jg + 1 <= rB) ? S[nt][3] * ATTN_SCALE : -30000.0f;
            }
        } else {
            #pragma unroll
            for (int nt = 0; nt < 8; nt++) {
                S[nt][0] *= ATTN_SCALE; S[nt][1] *= ATTN_SCALE;
                S[nt][2] *= ATTN_SCALE; S[nt][3] *= ATTN_SCALE;
            }
        }

        float bm0 = -INFINITY, bm1 = -INFINITY;
        #pragma unroll
        for (int nt = 0; nt < 8; nt++) {
            bm0 = fmaxf(bm0, fmaxf(S[nt][0], S[nt][1]));
            bm1 = fmaxf(bm1, fmaxf(S[nt][2], S[nt][3]));
        }
        bm0 = fmaxf(bm0, __shfl_xor_sync(0xffffffffu, bm0, 1));
        bm0 = fmaxf(bm0, __shfl_xor_sync(0xffffffffu, bm0, 2));
        bm1 = fmaxf(bm1, __shfl_xor_sync(0xffffffffu, bm1, 1));
        bm1 = fmaxf(bm1, __shfl_xor_sync(0xffffffffu, bm1, 2));
        float mn0 = fmaxf(m0, bm0);
        float mn1 = fmaxf(m1, bm1);

        float bs0 = 0.0f, bs1 = 0.0f;
        #pragma unroll
        for (int nt = 0; nt < 8; nt++) {
            S[nt][0] = __expf(S[nt][0] - mn0); bs0 += S[nt][0];
            S[nt][1] = __expf(S[nt][1] - mn0); bs0 += S[nt][1];
            S[nt][2] = __expf(S[nt][2] - mn1); bs1 += S[nt][2];
            S[nt][3] = __expf(S[nt][3] - mn1); bs1 += S[nt][3];
        }
        bs0 += __shfl_xor_sync(0xffffffffu, bs0, 1);
        bs0 += __shfl_xor_sync(0xffffffffu, bs0, 2);
        bs1 += __shfl_xor_sync(0xffffffffu, bs1, 1);
        bs1 += __shfl_xor_sync(0xffffffffu, bs1, 2);

        float a0 = __expf(m0 - mn0);
        float a1 = __expf(m1 - mn1);
        l0 = l0 * a0 + bs0;
        l1 = l1 * a1 + bs1;
        m0 = mn0; m1 = mn1;
        #pragma unroll
        for (int dt = 0; dt < 16; dt++) {
            O[dt][0] *= a0; O[dt][1] *= a0;
            O[dt][2] *= a1; O[dt][3] *= a1;
        }

        #pragma unroll
        for (int j = 0; j < 4; j++) {
            uint32_t pah[4], pal[4];
            pah[0] = pk2  (S[2*j][0],   S[2*j][1]);
            pah[1] = pk2  (S[2*j][2],   S[2*j][3]);
            pah[2] = pk2  (S[2*j+1][0], S[2*j+1][1]);
            pah[3] = pk2  (S[2*j+1][2], S[2*j+1][3]);
            pal[0] = pk2lo(S[2*j][0],   S[2*j][1]);
            pal[1] = pk2lo(S[2*j][2],   S[2*j][3]);
            pal[2] = pk2lo(S[2*j+1][0], S[2*j+1][1]);
            pal[3] = pk2lo(S[2*j+1][2], S[2*j+1][3]);
            #pragma unroll
            for (int dp = 0; dp < 8; dp++) {
                int vrow = dp * 16 + nIn;
                uint32_t va = VB + vrow * 128 + ((uint32_t)((cl ^ (vrow & 1)) << 4))
                            + (((uint32_t)j << 5) ^ ((uint32_t)(vrow & 6) << 4));
                uint32_t bh[4], bl[4];
                ldsm4(bh, va);
                ldsm4(bl, va + 16384);
                mma16816(O[2*dp],   pah, &bh[0]);
                mma16816(O[2*dp+1], pah, &bh[2]);
                mma16816(O[2*dp],   pah, &bl[0]);
                mma16816(O[2*dp+1], pah, &bl[2]);
                mma16816(O[2*dp],   pal, &bh[0]);
                mma16816(O[2*dp+1], pal, &bh[2]);
            }
        }
        __syncthreads();
    }

    float inv0 = 1.0f / l0;
    float inv1 = 1.0f / l1;
    size_t rowA = ((size_t)(b * Ts + rA)) * INNER + h * Dd;
    size_t rowB = ((size_t)(b * Ts + rB)) * INNER + h * Dd;
    #pragma unroll
    for (int dt = 0; dt < 16; dt++) {
        int col = dt * 8 + (lane & 3) * 2;
        float x0 = O[dt][0] * inv0, x1 = O[dt][1] * inv0;
        float y0 = O[dt][2] * inv1, y1 = O[dt][3] * inv1;
        *(uint32_t*)&oh[rowA + col] = pk2(x0, x1);
        *(uint32_t*)&ol[rowA + col] = pk2lo(x0, x1);
        *(uint32_t*)&oh[rowB + col] = pk2(y0, y1);
        *(uint32_t*)&ol[rowB + col] = pk2lo(y0, y1);
    }
}

// ---------------------------------------------------------------------------
// Launch  (order chosen so ncu -s 5 captures gemm_mma for wq)
// ---------------------------------------------------------------------------
extern "C" void kernel_launch(void* const* d_in, const int* in_sizes, int n_in,
                              void* d_out, int out_size)
{
    const float* stm  = (const float*)d_in[0];
    const float* wq   = (const float*)d_in[1];
    const float* wk   = (const float*)d_in[2];
    const float* wv   = (const float*)d_in[3];
    const float* wo   = (const float*)d_in[4];
    const float* cosv = (const float*)d_in[5];
    const float* sinv = (const float*)d_in[6];
    float* out = (float*)d_out;

    float *q, *k, *v;
    cudaGetSymbolAddress((void**)&q, g_q);
    cudaGetSymbolAddress((void**)&k, g_k);
    cudaGetSymbolAddress((void**)&v, g_v);
    unsigned short *xh, *xl, *wqh, *wql, *wkh, *wkl, *wvh, *wvl, *woh, *wol, *oh, *ol;
    cudaGetSymbolAddress((void**)&xh,  g_xh);  cudaGetSymbolAddress((void**)&xl,  g_xl);
    cudaGetSymbolAddress((void**)&wqh, g_wqh); cudaGetSymbolAddress((void**)&wql, g_wql);
    cudaGetSymbolAddress((void**)&wkh, g_wkh); cudaGetSymbolAddress((void**)&wkl, g_wkl);
    cudaGetSymbolAddress((void**)&wvh, g_wvh); cudaGetSymbolAddress((void**)&wvl, g_wvl);
    cudaGetSymbolAddress((void**)&woh, g_woh); cudaGetSymbolAddress((void**)&wol, g_wol);
    cudaGetSymbolAddress((void**)&oh,  g_oh);  cudaGetSymbolAddress((void**)&ol,  g_ol);
    unsigned short *qh2, *ql2, *kh2, *kl2, *vth, *vtl;
    cudaGetSymbolAddress((void**)&qh2, g_qh2); cudaGetSymbolAddress((void**)&ql2, g_ql2);
    cudaGetSymbolAddress((void**)&kh2, g_kh2); cudaGetSymbolAddress((void**)&kl2, g_kl2);
    cudaGetSymbolAddress((void**)&vth, g_vth); cudaGetSymbolAddress((void**)&vtl, g_vtl);

    cudaFuncSetAttribute(gemm_mma, cudaFuncAttributeMaxDynamicSharedMemorySize, GSMEM);
    cudaFuncSetAttribute(attn_mma, cudaFuncAttributeMaxDynamicSharedMemorySize, AT_SMEM);

    // 1: split activations
    split_kernel<<<MTOT*INNER/1024, 256>>>(stm, xh, xl, MTOT*INNER);
    // 2-4: transpose+split wq/wk/wv
    transpose_split<<<dim3(INNER/32, INNER/32), dim3(32,8)>>>(wq, wqh, wql, INNER, INNER);
    transpose_split<<<dim3(KVIN/32,  INNER/32), dim3(32,8)>>>(wk, wkh, wkl, INNER, KVIN);
    transpose_split<<<dim3(KVIN/32,  INNER/32), dim3(32,8)>>>(wv, wvh, wvl, INNER, KVIN);
    // 5: gemm_q  <-- ncu -s 5 captures this launch
    gemm_mma<<<dim3(INNER/128, MTOT/128), 256, GSMEM>>>(xh, xl, wqh, wql, q, INNER, INNER);
    // 6-7: gemm_k, gemm_v
    gemm_mma<<<dim3(KVIN/128,  MTOT/128), 256, GSMEM>>>(xh, xl, wkh, wkl, k, KVIN,  INNER);
    gemm_mma<<<dim3(KVIN/128,  MTOT/128), 256, GSMEM>>>(xh, xl, wvh, wvl, v, KVIN,  INNER);
    // 8: transpose+split wo (only needed before final gemm)
    transpose_split<<<dim3(INNER/32, INNER/32), dim3(32,8)>>>(wo, woh, wol, INNER, INNER);
    // 9-10: fused RoPE + split + relayout
    {
        int nq = Bb * Ts * Hq  * 64;
        int nk = Bb * Ts * Hkv * 64;
        rope_split<<<(nq + 255) / 256, 256>>>(q, cosv, sinv, qh2, ql2, Hq,  nq);
        rope_split<<<(nk + 255) / 256, 256>>>(k, cosv, sinv, kh2, kl2, Hkv, nk);
    }
    // 11: V transpose+split
    vtrans_split<<<dim3(Ts/32, Dd/32, Bb*Hkv), dim3(32,8)>>>(v, vth, vtl);
    // 12: attention
    attn_mma<<<dim3(Ts/128, Hq, Bb), 256, AT_SMEM>>>(qh2, ql2, kh2, kl2, vth, vtl, oh, ol);
    // 13: output projection
    gemm_mma<<<dim3(INNER/128, MTOT/128), 256, GSMEM>>>(oh, ol, woh, wol, out, INNER, INNER);
}

// round 7
// speedup vs baseline: 1.0997x; 1.0817x over previous
#include <cuda_runtime.h>
#include <cuda_bf16.h>
#include <math.h>
#include <stdint.h>

// Problem constants
#define Bb    2
#define Ts    2048
#define Hq    32
#define Hkv   8
#define Dd    128
#define INNER 4096
#define KVIN  1024
#define MTOT  4096              // B*T
#define ATTN_SCALE 0.08838834764831845f

// ---------------------------------------------------------------------------
// Scratch (device globals)
// ---------------------------------------------------------------------------
__device__ float g_q[Bb*Ts*Hq*Dd];
__device__ float g_k[Bb*Ts*Hkv*Dd];
__device__ float g_v[Bb*Ts*Hkv*Dd];

// bf16 split-precision operands (raw u16)
__device__ unsigned short g_xh [MTOT*INNER],  g_xl [MTOT*INNER];
__device__ unsigned short g_wqh[INNER*INNER], g_wql[INNER*INNER];
__device__ unsigned short g_wkh[KVIN*INNER],  g_wkl[KVIN*INNER];
__device__ unsigned short g_wvh[KVIN*INNER],  g_wvl[KVIN*INNER];
__device__ unsigned short g_woh[INNER*INNER], g_wol[INNER*INNER];
__device__ unsigned short g_oh [MTOT*INNER],  g_ol [MTOT*INNER];

// attention operands
__device__ unsigned short g_qh2[Bb*Hq*Ts*Dd],  g_ql2[Bb*Hq*Ts*Dd];    // [b,h,t,d]
__device__ unsigned short g_kh2[Bb*Hkv*Ts*Dd], g_kl2[Bb*Hkv*Ts*Dd];   // [b,hkv,t,d]
__device__ unsigned short g_vth[Bb*Hkv*Ts*Dd], g_vtl[Bb*Hkv*Ts*Dd];   // [b,hkv,d,t]

// ---------------------------------------------------------------------------
// Helpers
// ---------------------------------------------------------------------------
__device__ __forceinline__ uint32_t smem_u32(const void* p) {
    uint32_t a;
    asm("{ .reg .u64 t; cvta.to.shared.u64 t, %1; cvt.u32.u64 %0, t; }"
        : "=r"(a) : "l"(p));
    return a;
}
#define CPA16(d,s) asm volatile("cp.async.cg.shared.global [%0], [%1], 16;" :: "r"(d), "l"(s))
#define CPC()      asm volatile("cp.async.commit_group;" ::: "memory")
#define CPW(n)     asm volatile("cp.async.wait_group %0;" :: "n"(n) : "memory")

__device__ __forceinline__ void ldsm4(uint32_t* r, uint32_t a) {
    asm volatile("ldmatrix.sync.aligned.m8n8.x4.shared.b16 {%0,%1,%2,%3}, [%4];"
        : "=r"(r[0]), "=r"(r[1]), "=r"(r[2]), "=r"(r[3]) : "r"(a));
}
__device__ __forceinline__ void mma16816(float* c, const uint32_t* a, const uint32_t* b) {
    asm volatile("mma.sync.aligned.m16n8k16.row.col.f32.bf16.bf16.f32 "
        "{%0,%1,%2,%3}, {%4,%5,%6,%7}, {%8,%9}, {%0,%1,%2,%3};"
        : "+f"(c[0]), "+f"(c[1]), "+f"(c[2]), "+f"(c[3])
        : "r"(a[0]), "r"(a[1]), "r"(a[2]), "r"(a[3]), "r"(b[0]), "r"(b[1]));
}

__device__ __forceinline__ unsigned short f2bf(float x) {
    __nv_bfloat16 h = __float2bfloat16(x);
    return *reinterpret_cast<unsigned short*>(&h);
}
__device__ __forceinline__ float bf2f(unsigned short u) {
    __nv_bfloat16 h = *reinterpret_cast<__nv_bfloat16*>(&u);
    return __bfloat162float(h);
}
__device__ __forceinline__ uint32_t pk2(float a, float b) {
    return (uint32_t)f2bf(a) | ((uint32_t)f2bf(b) << 16);
}
__device__ __forceinline__ uint32_t pk2lo(float a, float b) {
    return pk2(a - bf2f(f2bf(a)), b - bf2f(f2bf(b)));
}

// ---------------------------------------------------------------------------
// Conversion kernels
// ---------------------------------------------------------------------------
__global__ void split_kernel(const float* __restrict__ x,
                             unsigned short* __restrict__ h,
                             unsigned short* __restrict__ l, int n)
{
    int i = (blockIdx.x * 256 + threadIdx.x) * 4;
    if (i >= n) return;
    float4 v = *(const float4*)(x + i);
    unsigned short h0 = f2bf(v.x), h1 = f2bf(v.y), h2 = f2bf(v.z), h3 = f2bf(v.w);
    ushort4 hh; hh.x = h0; hh.y = h1; hh.z = h2; hh.w = h3;
    *(ushort4*)(h + i) = hh;
    ushort4 ll;
    ll.x = f2bf(v.x - bf2f(h0)); ll.y = f2bf(v.y - bf2f(h1));
    ll.z = f2bf(v.z - bf2f(h2)); ll.w = f2bf(v.w - bf2f(h3));
    *(ushort4*)(l + i) = ll;
}

// w[K,N] -> out[N,K] (transpose) + hi/lo split
__global__ void transpose_split(const float* __restrict__ w,
                                unsigned short* __restrict__ th,
                                unsigned short* __restrict__ tl, int K, int N)
{
    __shared__ float t[32][33];
    int n0 = blockIdx.x * 32, k0 = blockIdx.y * 32;
    #pragma unroll
    for (int i = 0; i < 32; i += 8)
        t[threadIdx.y + i][threadIdx.x] =
            w[(size_t)(k0 + threadIdx.y + i) * N + n0 + threadIdx.x];
    __syncthreads();
    #pragma unroll
    for (int i = 0; i < 32; i += 8) {
        float x = t[threadIdx.x][threadIdx.y + i];
        size_t o = (size_t)(n0 + threadIdx.y + i) * K + k0 + threadIdx.x;
        unsigned short hb = f2bf(x);
        th[o] = hb;
        tl[o] = f2bf(x - bf2f(hb));
    }
}

// Fused: RoPE (rotate-half) + bf16 hi/lo split + relayout (b,t,HH,d)->(b,HH,t,d)
__global__ void rope_split(const float* __restrict__ buf,
                           const float* __restrict__ cs,
                           const float* __restrict__ sn,
                           unsigned short* __restrict__ dh,
                           unsigned short* __restrict__ dl,
                           int HH, int nPairs)
{
    int idx = blockIdx.x * blockDim.x + threadIdx.x;
    if (idx >= nPairs) return;
    int d    = idx & 63;
    int rest = idx >> 6;              // (b*Ts + t)*HH + h
    int h    = rest % HH;
    int bt   = rest / HH;
    int t    = bt & (Ts - 1);
    int b    = bt >> 11;              // Ts = 2048
    size_t ib = (size_t)rest * 128;
    float l = buf[ib + d];
    float r = buf[ib + d + 64];
    float c0 = cs[t * 128 + d],      s0 = sn[t * 128 + d];
    float c1 = cs[t * 128 + d + 64], s1 = sn[t * 128 + d + 64];
    float f0 = l * c0 - r * s0;
    float f1 = r * c1 + l * s1;
    size_t ob = ((size_t)((b * HH + h) * Ts + t)) << 7;
    unsigned short h0 = f2bf(f0);
    dh[ob + d] = h0;
    dl[ob + d] = f2bf(f0 - bf2f(h0));
    unsigned short h1 = f2bf(f1);
    dh[ob + d + 64] = h1;
    dl[ob + d + 64] = f2bf(f1 - bf2f(h1));
}

// g_v (b,t,hkv,d) fp32 -> (b,hkv,d,t) bf16 hi/lo
__global__ void vtrans_split(const float* __restrict__ v,
                             unsigned short* __restrict__ th,
                             unsigned short* __restrict__ tl)
{
    __shared__ float s[32][33];
    int t0 = blockIdx.x * 32, d0 = blockIdx.y * 32;
    int b = blockIdx.z >> 3, hk = blockIdx.z & 7;
    int tx = threadIdx.x, ty = threadIdx.y;
    #pragma unroll
    for (int i = 0; i < 32; i += 8)
        s[ty + i][tx] = v[((size_t)(b * Ts + t0 + ty + i) * Hkv + hk) * Dd + d0 + tx];
    __syncthreads();
    #pragma unroll
    for (int i = 0; i < 32; i += 8) {
        float x = s[tx][ty + i];
        size_t o = ((size_t)((b * Hkv + hk) * Dd + d0 + ty + i)) * Ts + t0 + tx;
        unsigned short hb = f2bf(x);
        th[o] = hb;
        tl[o] = f2bf(x - bf2f(hb));
    }
}

// ---------------------------------------------------------------------------
// mma.sync split-bf16 GEMM: C[M,N] = A[M,K] @ Bt[N,K]^T  (3-term split)
// CTA 128x128, 8 warps (warp tile 64m x 32n), K chunk 32.
// 3-stage cp.async pipeline, 96KB smem -> 2 CTAs/SM (16 warps/SM).
// B-fragments transient per-bt to stay under 128 regs/thread.
// ---------------------------------------------------------------------------
#define NSTG  3
#define STGB  32768
#define GSMEM (NSTG*STGB)

__global__ __launch_bounds__(256, 2) void gemm_mma(
    const unsigned short* __restrict__ Ah, const unsigned short* __restrict__ Al,
    const unsigned short* __restrict__ Bh, const unsigned short* __restrict__ Bl,
    float* __restrict__ C, int N, int K)
{
    extern __shared__ char smraw[];
    const uint32_t sb = smem_u32(smraw);
    const int tid  = threadIdx.x;
    const int wid  = tid >> 5;
    const int lane = tid & 31;
    const int mBase = blockIdx.y * 128;
    const int nBase = blockIdx.x * 128;
    const int warp_m = (wid & 1) * 64;
    const int warp_n = (wid >> 1) * 32;

    uint32_t aAddr[4], bAddr[2];
    {
        int r    = lane & 15;
        int half = lane >> 4;
        #pragma unroll
        for (int mt = 0; mt < 4; mt++) {
            int row = warp_m + mt * 16 + r;
            int sw  = (row >> 1) & 3;
            aAddr[mt] = sb + row * 64 + ((half ^ sw) << 4);
        }
        int nIn = (lane & 7) + (lane >> 4) * 8;
        int cl  = (lane >> 3) & 1;
        #pragma unroll
        for (int bt = 0; bt < 2; bt++) {
            int row = warp_n + bt * 16 + nIn;
            int sw  = (row >> 1) & 3;
            bAddr[bt] = sb + 16384 + row * 64 + ((cl ^ sw) << 4);
        }
    }

    const int ldRow = tid >> 2;
    const int ldC   = tid & 3;

    float cacc[4][4][4];
    #pragma unroll
    for (int a = 0; a < 4; a++)
        #pragma unroll
        for (int b = 0; b < 4; b++)
            #pragma unroll
            for (int c = 0; c < 4; c++) cacc[a][b][c] = 0.0f;

    const int NCH = K >> 5;

    auto load_chunk = [&](int st, int k0) {
        #pragma unroll
        for (int h = 0; h < 2; h++) {
            int row = ldRow + h * 64;
            int sw  = (row >> 1) & 3;
            uint32_t so = sb + st * STGB + row * 64 + ((ldC ^ sw) << 4);
            size_t ga = (size_t)(mBase + row) * K + k0 + ldC * 8;
            CPA16(so,         Ah + ga);
            CPA16(so + 8192,  Al + ga);
            size_t gb = (size_t)(nBase + row) * K + k0 + ldC * 8;
            CPA16(so + 16384, Bh + gb);
            CPA16(so + 24576, Bl + gb);
        }
        CPC();
    };

    load_chunk(0, 0);
    load_chunk(1, 32);

    int st = 0, ldst = 2;
    for (int i = 0; i < NCH; i++) {
        CPW(1);
        __syncthreads();
        uint32_t stOff = (uint32_t)st * STGB;

        #pragma unroll
        for (int s = 0; s < 2; s++) {
            uint32_t sx = (uint32_t)(s << 5);
            uint32_t a_hi[4][4], a_lo[4][4];
            #pragma unroll
            for (int mt = 0; mt < 4; mt++) {
                uint32_t ad = (aAddr[mt] ^ sx) + stOff;
                ldsm4(a_hi[mt], ad);
                ldsm4(a_lo[mt], ad + 8192);
            }
            #pragma unroll
            for (int bt = 0; bt < 2; bt++) {
                uint32_t bd = (bAddr[bt] ^ sx) + stOff;
                uint32_t b_hi[4], b_lo[4];
                ldsm4(b_hi, bd);
                ldsm4(b_lo, bd + 8192);
                #pragma unroll
                for (int mt = 0; mt < 4; mt++) {
                    mma16816(cacc[mt][bt*2],   a_hi[mt], &b_hi[0]);
                    mma16816(cacc[mt][bt*2+1], a_hi[mt], &b_hi[2]);
                    mma16816(cacc[mt][bt*2],   a_hi[mt], &b_lo[0]);
                    mma16816(cacc[mt][bt*2+1], a_hi[mt], &b_lo[2]);
                    mma16816(cacc[mt][bt*2],   a_lo[mt], &b_hi[0]);
                    mma16816(cacc[mt][bt*2+1], a_lo[mt], &b_hi[2]);
                }
            }
        }
        __syncthreads();
        int nx = i + 2;
        if (nx < NCH) load_chunk(ldst, nx << 5);
        else          CPC();
        if (++st   == NSTG) st   = 0;
        if (++ldst == NSTG) ldst = 0;
    }

    const int rBase = mBase + warp_m + (lane >> 2);
    const int cBase = nBase + warp_n + (lane & 3) * 2;
    #pragma unroll
    for (int mt = 0; mt < 4; mt++) {
        #pragma unroll
        for (int nt = 0; nt < 4; nt++) {
            int r0 = rBase + mt * 16;
            int c0 = cBase + nt * 8;
            float2 v0 = make_float2(cacc[mt][nt][0], cacc[mt][nt][1]);
            float2 v1 = make_float2(cacc[mt][nt][2], cacc[mt][nt][3]);
            *(float2*)&C[(size_t)r0 * N + c0]       = v0;
            *(float2*)&C[(size_t)(r0 + 8) * N + c0] = v1;
        }
    }
}

// ---------------------------------------------------------------------------
// Tensor-core flash attention, split-bf16 (3-term), causal GQA.
// ---------------------------------------------------------------------------
#define AT_SMEM 196608

__global__ __launch_bounds__(256, 1) void attn_mma(
    const unsigned short* __restrict__ qh, const unsigned short* __restrict__ ql,
    const unsigned short* __restrict__ kh, const unsigned short* __restrict__ kl,
    const unsigned short* __restrict__ vh, const unsigned short* __restrict__ vl,
    unsigned short* __restrict__ oh, unsigned short* __restrict__ ol)
{
    extern __shared__ char smraw[];
    const uint32_t sb = smem_u32(smraw);
    const uint32_t QHs = sb;
    const uint32_t STs = sb + 65536;

    const int tid = threadIdx.x, wid = tid >> 5, lane = tid & 31;
    const int qb = blockIdx.x, h = blockIdx.y, b = blockIdx.z;
    const int hk = h >> 2;
    const int qBase = qb * 128;
    const int nT = qb * 2 + 2;

    const unsigned short* Qhg = qh + ((size_t)(b * Hq + h) * Ts + qBase) * Dd;
    const unsigned short* Qlg = ql + ((size_t)(b * Hq + h) * Ts + qBase) * Dd;
    const unsigned short* Khg = kh + (size_t)(b * Hkv + hk) * Ts * Dd;
    const unsigned short* Klg = kl + (size_t)(b * Hkv + hk) * Ts * Dd;
    const unsigned short* Vhg = vh + (size_t)(b * Hkv + hk) * Dd * Ts;
    const unsigned short* Vlg = vl + (size_t)(b * Hkv + hk) * Dd * Ts;

    #pragma unroll
    for (int t = 0; t < 16; t++) {
        int idx = tid + t * 256;
        int arr = idx >> 11, rem = idx & 2047;
        int r = rem >> 4, c = rem & 15;
        uint32_t dst = QHs + arr * 32768 + r * 256 + ((c ^ (r & 7)) << 4);
        const unsigned short* s = (arr ? Qlg : Qhg) + (size_t)r * Dd + c * 8;
        CPA16(dst, s);
    }

    auto load_tile = [&](int st, int kt) {
        uint32_t base = STs + st * 65536;
        #pragma unroll
        for (int t = 0; t < 8; t++) {
            int idx = tid + t * 256;
            int arr = idx >> 10, rem = idx & 1023;
            int r = rem >> 4, c = rem & 15;
            uint32_t dst = base + arr * 16384 + r * 256 + ((c ^ (r & 7)) << 4);
            const unsigned short* s = (arr ? Klg : Khg) +
                (size_t)(kt * 64 + r) * Dd + c * 8;
            CPA16(dst, s);
        }
        #pragma unroll
        for (int t = 0; t < 8; t++) {
            int idx = tid + t * 256;
            int arr = idx >> 10, rem = idx & 1023;
            int r = rem >> 3, c = rem & 7;
            uint32_t dst = base + 32768 + arr * 16384 + r * 128 + ((c ^ (r & 7)) << 4);
            const unsigned short* s = (arr ? Vlg : Vhg) +
                (size_t)r * Ts + kt * 64 + c * 8;
            CPA16(dst, s);
        }
    };

    load_tile(0, 0);
    CPC();

    const int qrow = wid * 16 + (lane & 15);
    const uint32_t qpb = (uint32_t)(qrow * 256 + (((lane >> 4) ^ (qrow & 1)) << 4));
    const uint32_t qpx = (uint32_t)((qrow & 6) << 4);
    const int nIn = (lane & 7) + ((lane >> 4) << 3);
    const int cl  = (lane >> 3) & 1;

    float m0 = -INFINITY, m1 = -INFINITY, l0 = 0.0f, l1 = 0.0f;
    float O[16][4];
    #pragma unroll
    for (int i = 0; i < 16; i++)
        #pragma unroll
        for (int j = 0; j < 4; j++) O[i][j] = 0.0f;

    const int rA = qBase + wid * 16 + (lane >> 2);
    const int rB = rA + 8;

    for (int kt = 0; kt < nT; kt++) {
        if (kt + 1 < nT) { load_tile((kt + 1) & 1, kt + 1); CPC(); CPW(1); }
        else            { CPW(0); }
        __syncthreads();
        const uint32_t KB = STs + (kt & 1) * 65536;
        const uint32_t VB = KB + 32768;

        float S[8][4];
        #pragma unroll
        for (int i = 0; i < 8; i++)
            #pragma unroll
            for (int j = 0; j < 4; j++) S[i][j] = 0.0f;

        #pragma unroll
        for (int ks = 0; ks < 8; ks++) {
            uint32_t qa = QHs + qpb + (((uint32_t)ks << 5) ^ qpx);
            uint32_t ah[4], al[4];
            ldsm4(ah, qa);
            ldsm4(al, qa + 32768);
            #pragma unroll
            for (int np = 0; np < 4; np++) {
                int krow = np * 16 + nIn;
                uint32_t ka = KB + krow * 256 + ((uint32_t)((cl ^ (krow & 1)) << 4))
                            + (((uint32_t)ks << 5) ^ ((uint32_t)(krow & 6) << 4));
                uint32_t bh[4], bl[4];
                ldsm4(bh, ka);
                ldsm4(bl, ka + 16384);
                mma16816(S[2*np],   ah, &bh[0]);
                mma16816(S[2*np+1], ah, &bh[2]);
                mma16816(S[2*np],   ah, &bl[0]);
                mma16816(S[2*np+1], ah, &bl[2]);
                mma16816(S[2*np],   al, &bh[0]);
                mma16816(S[2*np+1], al, &bh[2]);
            }
        }

        if (kt >= 2 * qb) {
            #pragma unroll
            for (int nt = 0; nt < 8; nt++) {
                int jg = kt * 64 + nt * 8 + (lane & 3) * 2;
                S[nt][0] = (jg     <= rA) ? S[nt][0] * ATTN_SCALE : -30000.0f;
                S[nt][1] = (jg + 1 <= rA) ? S[nt][1] * ATTN_SCALE : -30000.0f;
                S[nt][2] = (jg     <= rB) ? S[nt][2] * ATTN_SCALE : -30000.0f;
                S[nt][3] = (jg + 1 <= rB) ? S[nt][3] * ATTN_SCALE : -30000.0f;
            }
        } else {
            #pragma unroll
            for (int nt = 0; nt < 8; nt++) {
                S[nt][0] *= ATTN_SCALE; S[nt][1] *= ATTN_SCALE;
                S[nt][2] *= ATTN_SCALE; S[nt][3] *= ATTN_SCALE;
            }
        }

        float bm0 = -INFINITY, bm1 = -INFINITY;
        #pragma unroll
        for (int nt = 0; nt < 8; nt++) {
            bm0 = fmaxf(bm0, fmaxf(S[nt][0], S[nt][1]));
            bm1 = fmaxf(bm1, fmaxf(S[nt][2], S[nt][3]));
        }
        bm0 = fmaxf(bm0, __shfl_xor_sync(0xffffffffu, bm0, 1));
        bm0 = fmaxf(bm0, __shfl_xor_sync(0xffffffffu, bm0, 2));
        bm1 = fmaxf(bm1, __shfl_xor_sync(0xffffffffu, bm1, 1));
        bm1 = fmaxf(bm1, __shfl_xor_sync(0xffffffffu, bm1, 2));
        float mn0 = fmaxf(m0, bm0);
        float mn1 = fmaxf(m1, bm1);

        float bs0 = 0.0f, bs1 = 0.0f;
        #pragma unroll
        for (int nt = 0; nt < 8; nt++) {
            S[nt][0] = __expf(S[nt][0] - mn0); bs0 += S[nt][0];
            S[nt][1] = __expf(S[nt][1] - mn0); bs0 += S[nt][1];
            S[nt][2] = __expf(S[nt][2] - mn1); bs1 += S[nt][2];
            S[nt][3] = __expf(S[nt][3] - mn1); bs1 += S[nt][3];
        }
        bs0 += __shfl_xor_sync(0xffffffffu, bs0, 1);
        bs0 += __shfl_xor_sync(0xffffffffu, bs0, 2);
        bs1 += __shfl_xor_sync(0xffffffffu, bs1, 1);
        bs1 += __shfl_xor_sync(0xffffffffu, bs1, 2);

        float a0 = __expf(m0 - mn0);
        float a1 = __expf(m1 - mn1);
        l0 = l0 * a0 + bs0;
        l1 = l1 * a1 + bs1;
        m0 = mn0; m1 = mn1;
        #pragma unroll
        for (int dt = 0; dt < 16; dt++) {
            O[dt][0] *= a0; O[dt][1] *= a0;
            O[dt][2] *= a1; O[dt][3] *= a1;
        }

        #pragma unroll
        for (int j = 0; j < 4; j++) {
            uint32_t pah[4], pal[4];
            pah[0] = pk2  (S[2*j][0],   S[2*j][1]);
            pah[1] = pk2  (S[2*j][2],   S[2*j][3]);
            pah[2] = pk2  (S[2*j+1][0], S[2*j+1][1]);
            pah[3] = pk2  (S[2*j+1][2], S[2*j+1][3]);
            pal[0] = pk2lo(S[2*j][0],   S[2*j][1]);
            pal[1] = pk2lo(S[2*j][2],   S[2*j][3]);
            pal[2] = pk2lo(S[2*j+1][0], S[2*j+1][1]);
            pal[3] = pk2lo(S[2*j+1][2], S[2*j+1][3]);
            #pragma unroll
            for (int dp = 0; dp < 8; dp++) {
                int vrow = dp * 16 + nIn;
                uint32_t va = VB + vrow * 128 + ((uint32_t)((cl ^ (vrow & 1)) << 4))
                            + (((uint32_t)j << 5) ^ ((uint32_t)(vrow & 6) << 4));
                uint32_t bh[4], bl[4];
                ldsm4(bh, va);
                ldsm4(bl, va + 16384);
                mma16816(O[2*dp],   pah, &bh[0]);
                mma16816(O[2*dp+1], pah, &bh[2]);
                mma16816(O[2*dp],   pah, &bl[0]);
                mma16816(O[2*dp+1], pah, &bl[2]);
                mma16816(O[2*dp],   pal, &bh[0]);
                mma16816(O[2*dp+1], pal, &bh[2]);
            }
        }
        __syncthreads();
    }

    float inv0 = 1.0f / l0;
    float inv1 = 1.0f / l1;
    size_t rowA = ((size_t)(b * Ts + rA)) * INNER + h * Dd;
    size_t rowB = ((size_t)(b * Ts + rB)) * INNER + h * Dd;
    #pragma unroll
    for (int dt = 0; dt < 16; dt++) {
        int col = dt * 8 + (lane & 3) * 2;
        float x0 = O[dt][0] * inv0, x1 = O[dt][1] * inv0;
        float y0 = O[dt][2] * inv1, y1 = O[dt][3] * inv1;
        *(uint32_t*)&oh[rowA + col] = pk2(x0, x1);
        *(uint32_t*)&ol[rowA + col] = pk2lo(x0, x1);
        *(uint32_t*)&oh[rowB + col] = pk2(y0, y1);
        *(uint32_t*)&ol[rowB + col] = pk2lo(y0, y1);
    }
}

// ---------------------------------------------------------------------------
// Launch
// ---------------------------------------------------------------------------
extern "C" void kernel_launch(void* const* d_in, const int* in_sizes, int n_in,
                              void* d_out, int out_size)
{
    const float* stm  = (const float*)d_in[0];
    const float* wq   = (const float*)d_in[1];
    const float* wk   = (const float*)d_in[2];
    const float* wv   = (const float*)d_in[3];
    const float* wo   = (const float*)d_in[4];
    const float* cosv = (const float*)d_in[5];
    const float* sinv = (const float*)d_in[6];
    float* out = (float*)d_out;

    float *q, *k, *v;
    cudaGetSymbolAddress((void**)&q, g_q);
    cudaGetSymbolAddress((void**)&k, g_k);
    cudaGetSymbolAddress((void**)&v, g_v);
    unsigned short *xh, *xl, *wqh, *wql, *wkh, *wkl, *wvh, *wvl, *woh, *wol, *oh, *ol;
    cudaGetSymbolAddress((void**)&xh,  g_xh);  cudaGetSymbolAddress((void**)&xl,  g_xl);
    cudaGetSymbolAddress((void**)&wqh, g_wqh); cudaGetSymbolAddress((void**)&wql, g_wql);
    cudaGetSymbolAddress((void**)&wkh, g_wkh); cudaGetSymbolAddress((void**)&wkl, g_wkl);
    cudaGetSymbolAddress((void**)&wvh, g_wvh); cudaGetSymbolAddress((void**)&wvl, g_wvl);
    cudaGetSymbolAddress((void**)&woh, g_woh); cudaGetSymbolAddress((void**)&wol, g_wol);
    cudaGetSymbolAddress((void**)&oh,  g_oh);  cudaGetSymbolAddress((void**)&ol,  g_ol);
    unsigned short *qh2, *ql2, *kh2, *kl2, *vth, *vtl;
    cudaGetSymbolAddress((void**)&qh2, g_qh2); cudaGetSymbolAddress((void**)&ql2, g_ql2);
    cudaGetSymbolAddress((void**)&kh2, g_kh2); cudaGetSymbolAddress((void**)&kl2, g_kl2);
    cudaGetSymbolAddress((void**)&vth, g_vth); cudaGetSymbolAddress((void**)&vtl, g_vtl);

    cudaFuncSetAttribute(gemm_mma, cudaFuncAttributeMaxDynamicSharedMemorySize, GSMEM);
    cudaFuncSetAttribute(attn_mma, cudaFuncAttributeMaxDynamicSharedMemorySize, AT_SMEM);

    // conversions (wq/wk/wv before QKV gemms)
    split_kernel<<<MTOT*INNER/1024, 256>>>(stm, xh, xl, MTOT*INNER);
    transpose_split<<<dim3(INNER/32, INNER/32), dim3(32,8)>>>(wq, wqh, wql, INNER, INNER);
    transpose_split<<<dim3(KVIN/32,  INNER/32), dim3(32,8)>>>(wk, wkh, wkl, INNER, KVIN);
    transpose_split<<<dim3(KVIN/32,  INNER/32), dim3(32,8)>>>(wv, wvh, wvl, INNER, KVIN);
    // QKV projections
    gemm_mma<<<dim3(INNER/128, MTOT/128), 256, GSMEM>>>(xh, xl, wqh, wql, q, INNER, INNER);
    gemm_mma<<<dim3(KVIN/128,  MTOT/128), 256, GSMEM>>>(xh, xl, wkh, wkl, k, KVIN,  INNER);
    gemm_mma<<<dim3(KVIN/128,  MTOT/128), 256, GSMEM>>>(xh, xl, wvh, wvl, v, KVIN,  INNER);
    // wo transpose (needed only before final gemm)
    transpose_split<<<dim3(INNER/32, INNER/32), dim3(32,8)>>>(wo, woh, wol, INNER, INNER);
    // fused RoPE + split + relayout
    {
        int nq = Bb * Ts * Hq  * 64;
        int nk = Bb * Ts * Hkv * 64;
        rope_split<<<(nq + 255) / 256, 256>>>(q, cosv, sinv, qh2, ql2, Hq,  nq);
        rope_split<<<(nk + 255) / 256, 256>>>(k, cosv, sinv, kh2, kl2, Hkv, nk);
    }
    vtrans_split<<<dim3(Ts/32, Dd/32, Bb*Hkv), dim3(32,8)>>>(v, vth, vtl);
    // attention
    attn_mma<<<dim3(Ts/128, Hq, Bb), 256, AT_SMEM>>>(qh2, ql2, kh2, kl2, vth, vtl, oh, ol);
    // output projection
    gemm_mma<<<dim3(INNER/128, MTOT/128), 256, GSMEM>>>(oh, ol, woh, wol, out, INNER, INNER);
}

// round 9
// speedup vs baseline: 1.1096x; 1.0090x over previous
#include <cuda_runtime.h>
#include <cuda_bf16.h>
#include <math.h>
#include <stdint.h>

// Problem constants
#define Bb    2
#define Ts    2048
#define Hq    32
#define Hkv   8
#define Dd    128
#define INNER 4096
#define KVIN  1024
#define MTOT  4096              // B*T
#define ATTN_SCALE 0.08838834764831845f

// ---------------------------------------------------------------------------
// Scratch (device globals)
// ---------------------------------------------------------------------------
__device__ float g_q[Bb*Ts*Hq*Dd];
__device__ float g_k[Bb*Ts*Hkv*Dd];
__device__ float g_v[Bb*Ts*Hkv*Dd];

// bf16 split-precision operands (raw u16)
__device__ unsigned short g_xh [MTOT*INNER],  g_xl [MTOT*INNER];
__device__ unsigned short g_wqh[INNER*INNER], g_wql[INNER*INNER];
__device__ unsigned short g_wkh[KVIN*INNER],  g_wkl[KVIN*INNER];
__device__ unsigned short g_wvh[KVIN*INNER],  g_wvl[KVIN*INNER];
__device__ unsigned short g_woh[INNER*INNER], g_wol[INNER*INNER];
__device__ unsigned short g_oh [MTOT*INNER],  g_ol [MTOT*INNER];

// attention operands
__device__ unsigned short g_qh2[Bb*Hq*Ts*Dd],  g_ql2[Bb*Hq*Ts*Dd];    // [b,h,t,d]
__device__ unsigned short g_kh2[Bb*Hkv*Ts*Dd], g_kl2[Bb*Hkv*Ts*Dd];   // [b,hkv,t,d]
__device__ unsigned short g_vth[Bb*Hkv*Ts*Dd], g_vtl[Bb*Hkv*Ts*Dd];   // [b,hkv,d,t]

// ---------------------------------------------------------------------------
// Helpers
// ---------------------------------------------------------------------------
__device__ __forceinline__ uint32_t smem_u32(const void* p) {
    uint32_t a;
    asm("{ .reg .u64 t; cvta.to.shared.u64 t, %1; cvt.u32.u64 %0, t; }"
        : "=r"(a) : "l"(p));
    return a;
}
#define CPA16(d,s) asm volatile("cp.async.cg.shared.global [%0], [%1], 16;" :: "r"(d), "l"(s))
#define CPC()      asm volatile("cp.async.commit_group;" ::: "memory")
#define CPW(n)     asm volatile("cp.async.wait_group %0;" :: "n"(n) : "memory")

__device__ __forceinline__ void ldsm4(uint32_t* r, uint32_t a) {
    asm volatile("ldmatrix.sync.aligned.m8n8.x4.shared.b16 {%0,%1,%2,%3}, [%4];"
        : "=r"(r[0]), "=r"(r[1]), "=r"(r[2]), "=r"(r[3]) : "r"(a));
}
__device__ __forceinline__ void mma16816(float* c, const uint32_t* a, const uint32_t* b) {
    asm volatile("mma.sync.aligned.m16n8k16.row.col.f32.bf16.bf16.f32 "
        "{%0,%1,%2,%3}, {%4,%5,%6,%7}, {%8,%9}, {%0,%1,%2,%3};"
        : "+f"(c[0]), "+f"(c[1]), "+f"(c[2]), "+f"(c[3])
        : "r"(a[0]), "r"(a[1]), "r"(a[2]), "r"(a[3]), "r"(b[0]), "r"(b[1]));
}

__device__ __forceinline__ unsigned short f2bf(float x) {
    __nv_bfloat16 h = __float2bfloat16(x);
    return *reinterpret_cast<unsigned short*>(&h);
}
__device__ __forceinline__ float bf2f(unsigned short u) {
    __nv_bfloat16 h = *reinterpret_cast<__nv_bfloat16*>(&u);
    return __bfloat162float(h);
}
__device__ __forceinline__ uint32_t pk2(float a, float b) {
    return (uint32_t)f2bf(a) | ((uint32_t)f2bf(b) << 16);
}
__device__ __forceinline__ uint32_t pk2lo(float a, float b) {
    return pk2(a - bf2f(f2bf(a)), b - bf2f(f2bf(b)));
}

// ---------------------------------------------------------------------------
// Conversion kernels
// ---------------------------------------------------------------------------
__global__ void split_kernel(const float* __restrict__ x,
                             unsigned short* __restrict__ h,
                             unsigned short* __restrict__ l, int n)
{
    int i = (blockIdx.x * 256 + threadIdx.x) * 4;
    if (i >= n) return;
    float4 v = *(const float4*)(x + i);
    unsigned short h0 = f2bf(v.x), h1 = f2bf(v.y), h2 = f2bf(v.z), h3 = f2bf(v.w);
    ushort4 hh; hh.x = h0; hh.y = h1; hh.z = h2; hh.w = h3;
    *(ushort4*)(h + i) = hh;
    ushort4 ll;
    ll.x = f2bf(v.x - bf2f(h0)); ll.y = f2bf(v.y - bf2f(h1));
    ll.z = f2bf(v.z - bf2f(h2)); ll.w = f2bf(v.w - bf2f(h3));
    *(ushort4*)(l + i) = ll;
}

// w[K,N] -> out[N,K] (transpose) + hi/lo split
__global__ void transpose_split(const float* __restrict__ w,
                                unsigned short* __restrict__ th,
                                unsigned short* __restrict__ tl, int K, int N)
{
    __shared__ float t[32][33];
    int n0 = blockIdx.x * 32, k0 = blockIdx.y * 32;
    #pragma unroll
    for (int i = 0; i < 32; i += 8)
        t[threadIdx.y + i][threadIdx.x] =
            w[(size_t)(k0 + threadIdx.y + i) * N + n0 + threadIdx.x];
    __syncthreads();
    #pragma unroll
    for (int i = 0; i < 32; i += 8) {
        float x = t[threadIdx.x][threadIdx.y + i];
        size_t o = (size_t)(n0 + threadIdx.y + i) * K + k0 + threadIdx.x;
        unsigned short hb = f2bf(x);
        th[o] = hb;
        tl[o] = f2bf(x - bf2f(hb));
    }
}

// Fused: RoPE (rotate-half) + bf16 hi/lo split + relayout (b,t,HH,d)->(b,HH,t,d)
__global__ void rope_split(const float* __restrict__ buf,
                           const float* __restrict__ cs,
                           const float* __restrict__ sn,
                           unsigned short* __restrict__ dh,
                           unsigned short* __restrict__ dl,
                           int HH, int nPairs)
{
    int idx = blockIdx.x * blockDim.x + threadIdx.x;
    if (idx >= nPairs) return;
    int d    = idx & 63;
    int rest = idx >> 6;              // (b*Ts + t)*HH + h
    int h    = rest % HH;
    int bt   = rest / HH;
    int t    = bt & (Ts - 1);
    int b    = bt >> 11;              // Ts = 2048
    size_t ib = (size_t)rest * 128;
    float l = buf[ib + d];
    float r = buf[ib + d + 64];
    float c0 = cs[t * 128 + d],      s0 = sn[t * 128 + d];
    float c1 = cs[t * 128 + d + 64], s1 = sn[t * 128 + d + 64];
    float f0 = l * c0 - r * s0;
    float f1 = r * c1 + l * s1;
    size_t ob = ((size_t)((b * HH + h) * Ts + t)) << 7;
    unsigned short h0 = f2bf(f0);
    dh[ob + d] = h0;
    dl[ob + d] = f2bf(f0 - bf2f(h0));
    unsigned short h1 = f2bf(f1);
    dh[ob + d + 64] = h1;
    dl[ob + d + 64] = f2bf(f1 - bf2f(h1));
}

// g_v (b,t,hkv,d) fp32 -> (b,hkv,d,t) bf16 hi/lo
__global__ void vtrans_split(const float* __restrict__ v,
                             unsigned short* __restrict__ th,
                             unsigned short* __restrict__ tl)
{
    __shared__ float s[32][33];
    int t0 = blockIdx.x * 32, d0 = blockIdx.y * 32;
    int b = blockIdx.z >> 3, hk = blockIdx.z & 7;
    int tx = threadIdx.x, ty = threadIdx.y;
    #pragma unroll
    for (int i = 0; i < 32; i += 8)
        s[ty + i][tx] = v[((size_t)(b * Ts + t0 + ty + i) * Hkv + hk) * Dd + d0 + tx];
    __syncthreads();
    #pragma unroll
    for (int i = 0; i < 32; i += 8) {
        float x = s[tx][ty + i];
        size_t o = ((size_t)((b * Hkv + hk) * Dd + d0 + ty + i)) * Ts + t0 + tx;
        unsigned short hb = f2bf(x);
        th[o] = hb;
        tl[o] = f2bf(x - bf2f(hb));
    }
}

// ---------------------------------------------------------------------------
// mma.sync split-bf16 GEMM: C[M,N] = A[M,K] @ Bt[N,K]^T  (3-term split)
// CTA 128x128, 8 warps (warp tile 64m x 32n), K chunk 32.
// 3-stage cp.async pipeline, 96KB smem -> 2 CTAs/SM (16 warps/SM).
// ONE barrier per chunk: CPW -> sync -> prefetch(i+2) -> compute.
// Safety: the prefetch at iter i overwrites stage (i+2)%3 == (i-1)%3, whose
// readers all ran in iter i-1 compute — program-order before they arrived at
// iter i's barrier, so write-after-read is barrier-ordered. (The analogous
// removal in attn_mma was a race — restored there.)
// ---------------------------------------------------------------------------
#define NSTG  3
#define STGB  32768
#define GSMEM (NSTG*STGB)

__global__ __launch_bounds__(256, 2) void gemm_mma(
    const unsigned short* __restrict__ Ah, const unsigned short* __restrict__ Al,
    const unsigned short* __restrict__ Bh, const unsigned short* __restrict__ Bl,
    float* __restrict__ C, int N, int K)
{
    extern __shared__ char smraw[];
    const uint32_t sb = smem_u32(smraw);
    const int tid  = threadIdx.x;
    const int wid  = tid >> 5;
    const int lane = tid & 31;
    const int mBase = blockIdx.y * 128;
    const int nBase = blockIdx.x * 128;
    const int warp_m = (wid & 1) * 64;
    const int warp_n = (wid >> 1) * 32;

    uint32_t aAddr[4], bAddr[2];
    {
        int r    = lane & 15;
        int half = lane >> 4;
        #pragma unroll
        for (int mt = 0; mt < 4; mt++) {
            int row = warp_m + mt * 16 + r;
            int sw  = (row >> 1) & 3;
            aAddr[mt] = sb + row * 64 + ((half ^ sw) << 4);
        }
        int nIn = (lane & 7) + (lane >> 4) * 8;
        int cl  = (lane >> 3) & 1;
        #pragma unroll
        for (int bt = 0; bt < 2; bt++) {
            int row = warp_n + bt * 16 + nIn;
            int sw  = (row >> 1) & 3;
            bAddr[bt] = sb + 16384 + row * 64 + ((cl ^ sw) << 4);
        }
    }

    const int ldRow = tid >> 2;
    const int ldC   = tid & 3;

    float cacc[4][4][4];
    #pragma unroll
    for (int a = 0; a < 4; a++)
        #pragma unroll
        for (int b = 0; b < 4; b++)
            #pragma unroll
            for (int c = 0; c < 4; c++) cacc[a][b][c] = 0.0f;

    const int NCH = K >> 5;

    auto load_chunk = [&](int st, int k0) {
        #pragma unroll
        for (int h = 0; h < 2; h++) {
            int row = ldRow + h * 64;
            int sw  = (row >> 1) & 3;
            uint32_t so = sb + st * STGB + row * 64 + ((ldC ^ sw) << 4);
            size_t ga = (size_t)(mBase + row) * K + k0 + ldC * 8;
            CPA16(so,         Ah + ga);
            CPA16(so + 8192,  Al + ga);
            size_t gb = (size_t)(nBase + row) * K + k0 + ldC * 8;
            CPA16(so + 16384, Bh + gb);
            CPA16(so + 24576, Bl + gb);
        }
        CPC();
    };

    load_chunk(0, 0);
    load_chunk(1, 32);

    int st = 0, ldst = 2;
    for (int i = 0; i < NCH; i++) {
        CPW(1);
        __syncthreads();
        // prefetch chunk i+2 into stage (i+2)%3 == (i-1)%3 (readers done)
        int nx = i + 2;
        if (nx < NCH) load_chunk(ldst, nx << 5);
        else          CPC();

        uint32_t stOff = (uint32_t)st * STGB;
        #pragma unroll
        for (int s = 0; s < 2; s++) {
            uint32_t sx = (uint32_t)(s << 5);
            uint32_t a_hi[4][4], a_lo[4][4];
            #pragma unroll
            for (int mt = 0; mt < 4; mt++) {
                uint32_t ad = (aAddr[mt] ^ sx) + stOff;
                ldsm4(a_hi[mt], ad);
                ldsm4(a_lo[mt], ad + 8192);
            }
            #pragma unroll
            for (int bt = 0; bt < 2; bt++) {
                uint32_t bd = (bAddr[bt] ^ sx) + stOff;
                uint32_t b_hi[4], b_lo[4];
                ldsm4(b_hi, bd);
                ldsm4(b_lo, bd + 8192);
                #pragma unroll
                for (int mt = 0; mt < 4; mt++) {
                    mma16816(cacc[mt][bt*2],   a_hi[mt], &b_hi[0]);
                    mma16816(cacc[mt][bt*2+1], a_hi[mt], &b_hi[2]);
                    mma16816(cacc[mt][bt*2],   a_hi[mt], &b_lo[0]);
                    mma16816(cacc[mt][bt*2+1], a_hi[mt], &b_lo[2]);
                    mma16816(cacc[mt][bt*2],   a_lo[mt], &b_hi[0]);
                    mma16816(cacc[mt][bt*2+1], a_lo[mt], &b_hi[2]);
                }
            }
        }
        if (++st   == NSTG) st   = 0;
        if (++ldst == NSTG) ldst = 0;
    }

    const int rBase = mBase + warp_m + (lane >> 2);
    const int cBase = nBase + warp_n + (lane & 3) * 2;
    #pragma unroll
    for (int mt = 0; mt < 4; mt++) {
        #pragma unroll
        for (int nt = 0; nt < 4; nt++) {
            int r0 = rBase + mt * 16;
            int c0 = cBase + nt * 8;
            float2 v0 = make_float2(cacc[mt][nt][0], cacc[mt][nt][1]);
            float2 v1 = make_float2(cacc[mt][nt][2], cacc[mt][nt][3]);
            *(float2*)&C[(size_t)r0 * N + c0]       = v0;
            *(float2*)&C[(size_t)(r0 + 8) * N + c0] = v1;
        }
    }
}

// ---------------------------------------------------------------------------
// Tensor-core flash attention, split-bf16 (3-term), causal GQA.
// Loop-end __syncthreads() is REQUIRED: without it, a fast warp's load of
// tile kt+2 (stage kt&1) at the next iteration top races slow warps still
// reading stage kt&1 in this iteration's PV (verified: round-8 rel_err 4e-3).
// ---------------------------------------------------------------------------
#define AT_SMEM 196608

__global__ __launch_bounds__(256, 1) void attn_mma(
    const unsigned short* __restrict__ qh, const unsigned short* __restrict__ ql,
    const unsigned short* __restrict__ kh, const unsigned short* __restrict__ kl,
    const unsigned short* __restrict__ vh, const unsigned short* __restrict__ vl,
    unsigned short* __restrict__ oh, unsigned short* __restrict__ ol)
{
    extern __shared__ char smraw[];
    const uint32_t sb = smem_u32(smraw);
    const uint32_t QHs = sb;
    const uint32_t STs = sb + 65536;

    const int tid = threadIdx.x, wid = tid >> 5, lane = tid & 31;
    const int qb = blockIdx.x, h = blockIdx.y, b = blockIdx.z;
    const int hk = h >> 2;
    const int qBase = qb * 128;
    const int nT = qb * 2 + 2;

    const unsigned short* Qhg = qh + ((size_t)(b * Hq + h) * Ts + qBase) * Dd;
    const unsigned short* Qlg = ql + ((size_t)(b * Hq + h) * Ts + qBase) * Dd;
    const unsigned short* Khg = kh + (size_t)(b * Hkv + hk) * Ts * Dd;
    const unsigned short* Klg = kl + (size_t)(b * Hkv + hk) * Ts * Dd;
    const unsigned short* Vhg = vh + (size_t)(b * Hkv + hk) * Dd * Ts;
    const unsigned short* Vlg = vl + (size_t)(b * Hkv + hk) * Dd * Ts;

    #pragma unroll
    for (int t = 0; t < 16; t++) {
        int idx = tid + t * 256;
        int arr = idx >> 11, rem = idx & 2047;
        int r = rem >> 4, c = rem & 15;
        uint32_t dst = QHs + arr * 32768 + r * 256 + ((c ^ (r & 7)) << 4);
        const unsigned short* s = (arr ? Qlg : Qhg) + (size_t)r * Dd + c * 8;
        CPA16(dst, s);
    }

    auto load_tile = [&](int st, int kt) {
        uint32_t base = STs + st * 65536;
        #pragma unroll
        for (int t = 0; t < 8; t++) {
            int idx = tid + t * 256;
            int arr = idx >> 10, rem = idx & 1023;
            int r = rem >> 4, c = rem & 15;
            uint32_t dst = base + arr * 16384 + r * 256 + ((c ^ (r & 7)) << 4);
            const unsigned short* s = (arr ? Klg : Khg) +
                (size_t)(kt * 64 + r) * Dd + c * 8;
            CPA16(dst, s);
        }
        #pragma unroll
        for (int t = 0; t < 8; t++) {
            int idx = tid + t * 256;
            int arr = idx >> 10, rem = idx & 1023;
            int r = rem >> 3, c = rem & 7;
            uint32_t dst = base + 32768 + arr * 16384 + r * 128 + ((c ^ (r & 7)) << 4);
            const unsigned short* s = (arr ? Vlg : Vhg) +
                (size_t)r * Ts + kt * 64 + c * 8;
            CPA16(dst, s);
        }
    };

    load_tile(0, 0);
    CPC();

    const int qrow = wid * 16 + (lane & 15);
    const uint32_t qpb = (uint32_t)(qrow * 256 + (((lane >> 4) ^ (qrow & 1)) << 4));
    const uint32_t qpx = (uint32_t)((qrow & 6) << 4);
    const int nIn = (lane & 7) + ((lane >> 4) << 3);
    const int cl  = (lane >> 3) & 1;

    float m0 = -INFINITY, m1 = -INFINITY, l0 = 0.0f, l1 = 0.0f;
    float O[16][4];
    #pragma unroll
    for (int i = 0; i < 16; i++)
        #pragma unroll
        for (int j = 0; j < 4; j++) O[i][j] = 0.0f;

    const int rA = qBase + wid * 16 + (lane >> 2);
    const int rB = rA + 8;

    for (int kt = 0; kt < nT; kt++) {
        if (kt + 1 < nT) { load_tile((kt + 1) & 1, kt + 1); CPC(); CPW(1); }
        else            { CPW(0); }
        __syncthreads();
        const uint32_t KB = STs + (kt & 1) * 65536;
        const uint32_t VB = KB + 32768;

        float S[8][4];
        #pragma unroll
        for (int i = 0; i < 8; i++)
            #pragma unroll
            for (int j = 0; j < 4; j++) S[i][j] = 0.0f;

        #pragma unroll
        for (int ks = 0; ks < 8; ks++) {
            uint32_t qa = QHs + qpb + (((uint32_t)ks << 5) ^ qpx);
            uint32_t ah[4], al[4];
            ldsm4(ah, qa);
            ldsm4(al, qa + 32768);
            #pragma unroll
            for (int np = 0; np < 4; np++) {
                int krow = np * 16 + nIn;
                uint32_t ka = KB + krow * 256 + ((uint32_t)((cl ^ (krow & 1)) << 4))
                            + (((uint32_t)ks << 5) ^ ((uint32_t)(krow & 6) << 4));
                uint32_t bh[4], bl[4];
                ldsm4(bh, ka);
                ldsm4(bl, ka + 16384);
                mma16816(S[2*np],   ah, &bh[0]);
                mma16816(S[2*np+1], ah, &bh[2]);
                mma16816(S[2*np],   ah, &bl[0]);
                mma16816(S[2*np+1], ah, &bl[2]);
                mma16816(S[2*np],   al, &bh[0]);
                mma16816(S[2*np+1], al, &bh[2]);
            }
        }

        if (kt >= 2 * qb) {
            #pragma unroll
            for (int nt = 0; nt < 8; nt++) {
                int jg = kt * 64 + nt * 8 + (lane & 3) * 2;
                S[nt][0] = (jg     <= rA) ? S[nt][0] * ATTN_SCALE : -30000.0f;
                S[nt][1] = (jg + 1 <= rA) ? S[nt][1] * ATTN_SCALE : -30000.0f;
                S[nt][2] = (jg     <= rB) ? S[nt][2] * ATTN_SCALE : -30000.0f;
                S[nt][3] = (jg + 1 <= rB) ? S[nt][3] * ATTN_SCALE : -30000.0f;
            }
        } else {
            #pragma unroll
            for (int nt = 0; nt < 8; nt++) {
                S[nt][0] *= ATTN_SCALE; S[nt][1] *= ATTN_SCALE;
                S[nt][2] *= ATTN_SCALE; S[nt][3] *= ATTN_SCALE;
            }
        }

        float bm0 = -INFINITY, bm1 = -INFINITY;
        #pragma unroll
        for (int nt = 0; nt < 8; nt++) {
            bm0 = fmaxf(bm0, fmaxf(S[nt][0], S[nt][1]));
            bm1 = fmaxf(bm1, fmaxf(S[nt][2], S[nt][3]));
        }
        bm0 = fmaxf(bm0, __shfl_xor_sync(0xffffffffu, bm0, 1));
        bm0 = fmaxf(bm0, __shfl_xor_sync(0xffffffffu, bm0, 2));
        bm1 = fmaxf(bm1, __shfl_xor_sync(0xffffffffu, bm1, 1));
        bm1 = fmaxf(bm1, __shfl_xor_sync(0xffffffffu, bm1, 2));
        float mn0 = fmaxf(m0, bm0);
        float mn1 = fmaxf(m1, bm1);

        float bs0 = 0.0f, bs1 = 0.0f;
        #pragma unroll
        for (int nt = 0; nt < 8; nt++) {
            S[nt][0] = __expf(S[nt][0] - mn0); bs0 += S[nt][0];
            S[nt][1] = __expf(S[nt][1] - mn0); bs0 += S[nt][1];
            S[nt][2] = __expf(S[nt][2] - mn1); bs1 += S[nt][2];
            S[nt][3] = __expf(S[nt][3] - mn1); bs1 += S[nt][3];
        }
        bs0 += __shfl_xor_sync(0xffffffffu, bs0, 1);
        bs0 += __shfl_xor_sync(0xffffffffu, bs0, 2);
        bs1 += __shfl_xor_sync(0xffffffffu, bs1, 1);
        bs1 += __shfl_xor_sync(0xffffffffu, bs1, 2);

        float a0 = __expf(m0 - mn0);
        float a1 = __expf(m1 - mn1);
        l0 = l0 * a0 + bs0;
        l1 = l1 * a1 + bs1;
        m0 = mn0; m1 = mn1;
        #pragma unroll
        for (int dt = 0; dt < 16; dt++) {
            O[dt][0] *= a0; O[dt][1] *= a0;
            O[dt][2] *= a1; O[dt][3] *= a1;
        }

        #pragma unroll
        for (int j = 0; j < 4; j++) {
            uint32_t pah[4], pal[4];
            pah[0] = pk2  (S[2*j][0],   S[2*j][1]);
            pah[1] = pk2  (S[2*j][2],   S[2*j][3]);
            pah[2] = pk2  (S[2*j+1][0], S[2*j+1][1]);
            pah[3] = pk2  (S[2*j+1][2], S[2*j+1][3]);
            pal[0] = pk2lo(S[2*j][0],   S[2*j][1]);
            pal[1] = pk2lo(S[2*j][2],   S[2*j][3]);
            pal[2] = pk2lo(S[2*j+1][0], S[2*j+1][1]);
            pal[3] = pk2lo(S[2*j+1][2], S[2*j+1][3]);
            #pragma unroll
            for (int dp = 0; dp < 8; dp++) {
                int vrow = dp * 16 + nIn;
                uint32_t va = VB + vrow * 128 + ((uint32_t)((cl ^ (vrow & 1)) << 4))
                            + (((uint32_t)j << 5) ^ ((uint32_t)(vrow & 6) << 4));
                uint32_t bh[4], bl[4];
                ldsm4(bh, va);
                ldsm4(bl, va + 16384);
                mma16816(O[2*dp],   pah, &bh[0]);
                mma16816(O[2*dp+1], pah, &bh[2]);
                mma16816(O[2*dp],   pah, &bl[0]);
                mma16816(O[2*dp+1], pah, &bl[2]);
                mma16816(O[2*dp],   pal, &bh[0]);
                mma16816(O[2*dp+1], pal, &bh[2]);
            }
        }
        __syncthreads();   // REQUIRED write-after-read guard (see header)
    }

    float inv0 = 1.0f / l0;
    float inv1 = 1.0f / l1;
    size_t rowA = ((size_t)(b * Ts + rA)) * INNER + h * Dd;
    size_t rowB = ((size_t)(b * Ts + rB)) * INNER + h * Dd;
    #pragma unroll
    for (int dt = 0; dt < 16; dt++) {
        int col = dt * 8 + (lane & 3) * 2;
        float x0 = O[dt][0] * inv0, x1 = O[dt][1] * inv0;
        float y0 = O[dt][2] * inv1, y1 = O[dt][3] * inv1;
        *(uint32_t*)&oh[rowA + col] = pk2(x0, x1);
        *(uint32_t*)&ol[rowA + col] = pk2lo(x0, x1);
        *(uint32_t*)&oh[rowB + col] = pk2(y0, y1);
        *(uint32_t*)&ol[rowB + col] = pk2lo(y0, y1);
    }
}

// ---------------------------------------------------------------------------
// Launch
// ---------------------------------------------------------------------------
extern "C" void kernel_launch(void* const* d_in, const int* in_sizes, int n_in,
                              void* d_out, int out_size)
{
    const float* stm  = (const float*)d_in[0];
    const float* wq   = (const float*)d_in[1];
    const float* wk   = (const float*)d_in[2];
    const float* wv   = (const float*)d_in[3];
    const float* wo   = (const float*)d_in[4];
    const float* cosv = (const float*)d_in[5];
    const float* sinv = (const float*)d_in[6];
    float* out = (float*)d_out;

    float *q, *k, *v;
    cudaGetSymbolAddress((void**)&q, g_q);
    cudaGetSymbolAddress((void**)&k, g_k);
    cudaGetSymbolAddress((void**)&v, g_v);
    unsigned short *xh, *xl, *wqh, *wql, *wkh, *wkl, *wvh, *wvl, *woh, *wol, *oh, *ol;
    cudaGetSymbolAddress((void**)&xh,  g_xh);  cudaGetSymbolAddress((void**)&xl,  g_xl);
    cudaGetSymbolAddress((void**)&wqh, g_wqh); cudaGetSymbolAddress((void**)&wql, g_wql);
    cudaGetSymbolAddress((void**)&wkh, g_wkh); cudaGetSymbolAddress((void**)&wkl, g_wkl);
    cudaGetSymbolAddress((void**)&wvh, g_wvh); cudaGetSymbolAddress((void**)&wvl, g_wvl);
    cudaGetSymbolAddress((void**)&woh, g_woh); cudaGetSymbolAddress((void**)&wol, g_wol);
    cudaGetSymbolAddress((void**)&oh,  g_oh);  cudaGetSymbolAddress((void**)&ol,  g_ol);
    unsigned short *qh2, *ql2, *kh2, *kl2, *vth, *vtl;
    cudaGetSymbolAddress((void**)&qh2, g_qh2); cudaGetSymbolAddress((void**)&ql2, g_ql2);
    cudaGetSymbolAddress((void**)&kh2, g_kh2); cudaGetSymbolAddress((void**)&kl2, g_kl2);
    cudaGetSymbolAddress((void**)&vth, g_vth); cudaGetSymbolAddress((void**)&vtl, g_vtl);

    cudaFuncSetAttribute(gemm_mma, cudaFuncAttributeMaxDynamicSharedMemorySize, GSMEM);
    cudaFuncSetAttribute(attn_mma, cudaFuncAttributeMaxDynamicSharedMemorySize, AT_SMEM);

    // conversions (wq/wk/wv before QKV gemms)
    split_kernel<<<MTOT*INNER/1024, 256>>>(stm, xh, xl, MTOT*INNER);
    transpose_split<<<dim3(INNER/32, INNER/32), dim3(32,8)>>>(wq, wqh, wql, INNER, INNER);
    transpose_split<<<dim3(KVIN/32,  INNER/32), dim3(32,8)>>>(wk, wkh, wkl, INNER, KVIN);
    transpose_split<<<dim3(KVIN/32,  INNER/32), dim3(32,8)>>>(wv, wvh, wvl, INNER, KVIN);
    // QKV projections
    gemm_mma<<<dim3(INNER/128, MTOT/128), 256, GSMEM>>>(xh, xl, wqh, wql, q, INNER, INNER);
    gemm_mma<<<dim3(KVIN/128,  MTOT/128), 256, GSMEM>>>(xh, xl, wkh, wkl, k, KVIN,  INNER);
    gemm_mma<<<dim3(KVIN/128,  MTOT/128), 256, GSMEM>>>(xh, xl, wvh, wvl, v, KVIN,  INNER);
    // wo transpose (needed only before final gemm)
    transpose_split<<<dim3(INNER/32, INNER/32), dim3(32,8)>>>(wo, woh, wol, INNER, INNER);
    // fused RoPE + split + relayout
    {
        int nq = Bb * Ts * Hq  * 64;
        int nk = Bb * Ts * Hkv * 64;
        rope_split<<<(nq + 255) / 256, 256>>>(q, cosv, sinv, qh2, ql2, Hq,  nq);
        rope_split<<<(nk + 255) / 256, 256>>>(k, cosv, sinv, kh2, kl2, Hkv, nk);
    }
    vtrans_split<<<dim3(Ts/32, Dd/32, Bb*Hkv), dim3(32,8)>>>(v, vth, vtl);
    // attention
    attn_mma<<<dim3(Ts/128, Hq, Bb), 256, AT_SMEM>>>(qh2, ql2, kh2, kl2, vth, vtl, oh, ol);
    // output projection
    gemm_mma<<<dim3(INNER/128, MTOT/128), 256, GSMEM>>>(oh, ol, woh, wol, out, INNER, INNER);
}

// round 10
// speedup vs baseline: 1.1236x; 1.0127x over previous
#include <cuda_runtime.h>
#include <cuda_bf16.h>
#include <math.h>
#include <stdint.h>

// Problem constants
#define Bb    2
#define Ts    2048
#define Hq    32
#define Hkv   8
#define Dd    128
#define INNER 4096
#define KVIN  1024
#define QKVN  6144              // 4096 (q) + 1024 (k) + 1024 (v)
#define MTOT  4096              // B*T
#define ATTN_SCALE 0.08838834764831845f

// ---------------------------------------------------------------------------
// Scratch (device globals)
// ---------------------------------------------------------------------------
__device__ float g_qkv[MTOT*QKVN];   // fused QKV projection output (fp32)

// bf16 split-precision operands (raw u16)
__device__ unsigned short g_xh [MTOT*INNER],  g_xl [MTOT*INNER];
__device__ unsigned short g_wah[QKVN*INNER],  g_wal[QKVN*INNER];   // [wq;wk;wv]^T rows
__device__ unsigned short g_woh[INNER*INNER], g_wol[INNER*INNER];
__device__ unsigned short g_oh [MTOT*INNER],  g_ol [MTOT*INNER];

// attention operands
__device__ unsigned short g_qh2[Bb*Hq*Ts*Dd],  g_ql2[Bb*Hq*Ts*Dd];    // [b,h,t,d]
__device__ unsigned short g_kh2[Bb*Hkv*Ts*Dd], g_kl2[Bb*Hkv*Ts*Dd];   // [b,hkv,t,d]
__device__ unsigned short g_vth[Bb*Hkv*Ts*Dd], g_vtl[Bb*Hkv*Ts*Dd];   // [b,hkv,d,t]

// ---------------------------------------------------------------------------
// Helpers
// ---------------------------------------------------------------------------
__device__ __forceinline__ uint32_t smem_u32(const void* p) {
    uint32_t a;
    asm("{ .reg .u64 t; cvta.to.shared.u64 t, %1; cvt.u32.u64 %0, t; }"
        : "=r"(a) : "l"(p));
    return a;
}
#define CPA16(d,s) asm volatile("cp.async.cg.shared.global [%0], [%1], 16;" :: "r"(d), "l"(s))
#define CPC()      asm volatile("cp.async.commit_group;" ::: "memory")
#define CPW(n)     asm volatile("cp.async.wait_group %0;" :: "n"(n) : "memory")

__device__ __forceinline__ void ldsm4(uint32_t* r, uint32_t a) {
    asm volatile("ldmatrix.sync.aligned.m8n8.x4.shared.b16 {%0,%1,%2,%3}, [%4];"
        : "=r"(r[0]), "=r"(r[1]), "=r"(r[2]), "=r"(r[3]) : "r"(a));
}
__device__ __forceinline__ void mma16816(float* c, const uint32_t* a, const uint32_t* b) {
    asm volatile("mma.sync.aligned.m16n8k16.row.col.f32.bf16.bf16.f32 "
        "{%0,%1,%2,%3}, {%4,%5,%6,%7}, {%8,%9}, {%0,%1,%2,%3};"
        : "+f"(c[0]), "+f"(c[1]), "+f"(c[2]), "+f"(c[3])
        : "r"(a[0]), "r"(a[1]), "r"(a[2]), "r"(a[3]), "r"(b[0]), "r"(b[1]));
}

__device__ __forceinline__ unsigned short f2bf(float x) {
    __nv_bfloat16 h = __float2bfloat16(x);
    return *reinterpret_cast<unsigned short*>(&h);
}
__device__ __forceinline__ float bf2f(unsigned short u) {
    __nv_bfloat16 h = *reinterpret_cast<__nv_bfloat16*>(&u);
    return __bfloat162float(h);
}
__device__ __forceinline__ uint32_t pk2(float a, float b) {
    return (uint32_t)f2bf(a) | ((uint32_t)f2bf(b) << 16);
}
__device__ __forceinline__ uint32_t pk2lo(float a, float b) {
    return pk2(a - bf2f(f2bf(a)), b - bf2f(f2bf(b)));
}

// ---------------------------------------------------------------------------
// Conversion kernels
// ---------------------------------------------------------------------------
__global__ void split_kernel(const float* __restrict__ x,
                             unsigned short* __restrict__ h,
                             unsigned short* __restrict__ l, int n)
{
    int i = (blockIdx.x * 256 + threadIdx.x) * 4;
    if (i >= n) return;
    float4 v = *(const float4*)(x + i);
    unsigned short h0 = f2bf(v.x), h1 = f2bf(v.y), h2 = f2bf(v.z), h3 = f2bf(v.w);
    ushort4 hh; hh.x = h0; hh.y = h1; hh.z = h2; hh.w = h3;
    *(ushort4*)(h + i) = hh;
    ushort4 ll;
    ll.x = f2bf(v.x - bf2f(h0)); ll.y = f2bf(v.y - bf2f(h1));
    ll.z = f2bf(v.z - bf2f(h2)); ll.w = f2bf(v.w - bf2f(h3));
    *(ushort4*)(l + i) = ll;
}

// w[K,N] -> out[N,K] (transpose) + hi/lo split
__global__ void transpose_split(const float* __restrict__ w,
                                unsigned short* __restrict__ th,
                                unsigned short* __restrict__ tl, int K, int N)
{
    __shared__ float t[32][33];
    int n0 = blockIdx.x * 32, k0 = blockIdx.y * 32;
    #pragma unroll
    for (int i = 0; i < 32; i += 8)
        t[threadIdx.y + i][threadIdx.x] =
            w[(size_t)(k0 + threadIdx.y + i) * N + n0 + threadIdx.x];
    __syncthreads();
    #pragma unroll
    for (int i = 0; i < 32; i += 8) {
        float x = t[threadIdx.x][threadIdx.y + i];
        size_t o = (size_t)(n0 + threadIdx.y + i) * K + k0 + threadIdx.x;
        unsigned short hb = f2bf(x);
        th[o] = hb;
        tl[o] = f2bf(x - bf2f(hb));
    }
}

// Fused: RoPE + bf16 hi/lo split + relayout, reading from the fused-QKV
// buffer (row stride QKVN, column offset colOff) -> (b,HH,t,d)
__global__ void rope_split(const float* __restrict__ qkv,
                           const float* __restrict__ cs,
                           const float* __restrict__ sn,
                           unsigned short* __restrict__ dh,
                           unsigned short* __restrict__ dl,
                           int HH, int colOff, int nPairs)
{
    int idx = blockIdx.x * blockDim.x + threadIdx.x;
    if (idx >= nPairs) return;
    int d    = idx & 63;
    int rest = idx >> 6;              // (b*Ts + t)*HH + h
    int h    = rest % HH;
    int bt   = rest / HH;
    int t    = bt & (Ts - 1);
    int b    = bt >> 11;              // Ts = 2048
    size_t ib = (size_t)bt * QKVN + colOff + h * 128;
    float l = qkv[ib + d];
    float r = qkv[ib + d + 64];
    float c0 = cs[t * 128 + d],      s0 = sn[t * 128 + d];
    float c1 = cs[t * 128 + d + 64], s1 = sn[t * 128 + d + 64];
    float f0 = l * c0 - r * s0;
    float f1 = r * c1 + l * s1;
    size_t ob = ((size_t)((b * HH + h) * Ts + t)) << 7;
    unsigned short h0 = f2bf(f0);
    dh[ob + d] = h0;
    dl[ob + d] = f2bf(f0 - bf2f(h0));
    unsigned short h1 = f2bf(f1);
    dh[ob + d + 64] = h1;
    dl[ob + d + 64] = f2bf(f1 - bf2f(h1));
}

// v slice of g_qkv (cols 5120+) -> (b,hkv,d,t) bf16 hi/lo
__global__ void vtrans_split(const float* __restrict__ qkv,
                             unsigned short* __restrict__ th,
                             unsigned short* __restrict__ tl)
{
    __shared__ float s[32][33];
    int t0 = blockIdx.x * 32, d0 = blockIdx.y * 32;
    int b = blockIdx.z >> 3, hk = blockIdx.z & 7;
    int tx = threadIdx.x, ty = threadIdx.y;
    #pragma unroll
    for (int i = 0; i < 32; i += 8)
        s[ty + i][tx] = qkv[(size_t)(b * Ts + t0 + ty + i) * QKVN
                            + (INNER + KVIN) + hk * Dd + d0 + tx];
    __syncthreads();
    #pragma unroll
    for (int i = 0; i < 32; i += 8) {
        float x = s[tx][ty + i];
        size_t o = ((size_t)((b * Hkv + hk) * Dd + d0 + ty + i)) * Ts + t0 + tx;
        unsigned short hb = f2bf(x);
        th[o] = hb;
        tl[o] = f2bf(x - bf2f(hb));
    }
}

// ---------------------------------------------------------------------------
// mma.sync split-bf16 GEMM: C[M,N] = A[M,K] @ Bt[N,K]^T  (3-term split)
// CTA 128x128, 8 warps (warp tile 64m x 32n), K chunk 32.
// 3-stage cp.async pipeline, 96KB smem -> 2 CTAs/SM (16 warps/SM).
// ONE barrier per chunk: CPW -> sync -> prefetch(i+2) -> compute (verified
// safe: the stage being overwritten was last read before this barrier).
// ---------------------------------------------------------------------------
#define NSTG  3
#define STGB  32768
#define GSMEM (NSTG*STGB)

__global__ __launch_bounds__(256, 2) void gemm_mma(
    const unsigned short* __restrict__ Ah, const unsigned short* __restrict__ Al,
    const unsigned short* __restrict__ Bh, const unsigned short* __restrict__ Bl,
    float* __restrict__ C, int N, int K)
{
    extern __shared__ char smraw[];
    const uint32_t sb = smem_u32(smraw);
    const int tid  = threadIdx.x;
    const int wid  = tid >> 5;
    const int lane = tid & 31;
    const int mBase = blockIdx.y * 128;
    const int nBase = blockIdx.x * 128;
    const int warp_m = (wid & 1) * 64;
    const int warp_n = (wid >> 1) * 32;

    uint32_t aAddr[4], bAddr[2];
    {
        int r    = lane & 15;
        int half = lane >> 4;
        #pragma unroll
        for (int mt = 0; mt < 4; mt++) {
            int row = warp_m + mt * 16 + r;
            int sw  = (row >> 1) & 3;
            aAddr[mt] = sb + row * 64 + ((half ^ sw) << 4);
        }
        int nIn = (lane & 7) + (lane >> 4) * 8;
        int cl  = (lane >> 3) & 1;
        #pragma unroll
        for (int bt = 0; bt < 2; bt++) {
            int row = warp_n + bt * 16 + nIn;
            int sw  = (row >> 1) & 3;
            bAddr[bt] = sb + 16384 + row * 64 + ((cl ^ sw) << 4);
        }
    }

    const int ldRow = tid >> 2;
    const int ldC   = tid & 3;

    float cacc[4][4][4];
    #pragma unroll
    for (int a = 0; a < 4; a++)
        #pragma unroll
        for (int b = 0; b < 4; b++)
            #pragma unroll
            for (int c = 0; c < 4; c++) cacc[a][b][c] = 0.0f;

    const int NCH = K >> 5;

    auto load_chunk = [&](int st, int k0) {
        #pragma unroll
        for (int h = 0; h < 2; h++) {
            int row = ldRow + h * 64;
            int sw  = (row >> 1) & 3;
            uint32_t so = sb + st * STGB + row * 64 + ((ldC ^ sw) << 4);
            size_t ga = (size_t)(mBase + row) * K + k0 + ldC * 8;
            CPA16(so,         Ah + ga);
            CPA16(so + 8192,  Al + ga);
            size_t gb = (size_t)(nBase + row) * K + k0 + ldC * 8;
            CPA16(so + 16384, Bh + gb);
            CPA16(so + 24576, Bl + gb);
        }
        CPC();
    };

    load_chunk(0, 0);
    load_chunk(1, 32);

    int st = 0, ldst = 2;
    for (int i = 0; i < NCH; i++) {
        CPW(1);
        __syncthreads();
        int nx = i + 2;
        if (nx < NCH) load_chunk(ldst, nx << 5);
        else          CPC();

        uint32_t stOff = (uint32_t)st * STGB;
        #pragma unroll
        for (int s = 0; s < 2; s++) {
            uint32_t sx = (uint32_t)(s << 5);
            uint32_t a_hi[4][4], a_lo[4][4];
            #pragma unroll
            for (int mt = 0; mt < 4; mt++) {
                uint32_t ad = (aAddr[mt] ^ sx) + stOff;
                ldsm4(a_hi[mt], ad);
                ldsm4(a_lo[mt], ad + 8192);
            }
            #pragma unroll
            for (int bt = 0; bt < 2; bt++) {
                uint32_t bd = (bAddr[bt] ^ sx) + stOff;
                uint32_t b_hi[4], b_lo[4];
                ldsm4(b_hi, bd);
                ldsm4(b_lo, bd + 8192);
                #pragma unroll
                for (int mt = 0; mt < 4; mt++) {
                    mma16816(cacc[mt][bt*2],   a_hi[mt], &b_hi[0]);
                    mma16816(cacc[mt][bt*2+1], a_hi[mt], &b_hi[2]);
                    mma16816(cacc[mt][bt*2],   a_hi[mt], &b_lo[0]);
                    mma16816(cacc[mt][bt*2+1], a_hi[mt], &b_lo[2]);
                    mma16816(cacc[mt][bt*2],   a_lo[mt], &b_hi[0]);
                    mma16816(cacc[mt][bt*2+1], a_lo[mt], &b_hi[2]);
                }
            }
        }
        if (++st   == NSTG) st   = 0;
        if (++ldst == NSTG) ldst = 0;
    }

    const int rBase = mBase + warp_m + (lane >> 2);
    const int cBase = nBase + warp_n + (lane & 3) * 2;
    #pragma unroll
    for (int mt = 0; mt < 4; mt++) {
        #pragma unroll
        for (int nt = 0; nt < 4; nt++) {
            int r0 = rBase + mt * 16;
            int c0 = cBase + nt * 8;
            float2 v0 = make_float2(cacc[mt][nt][0], cacc[mt][nt][1]);
            float2 v1 = make_float2(cacc[mt][nt][2], cacc[mt][nt][3]);
            *(float2*)&C[(size_t)r0 * N + c0]       = v0;
            *(float2*)&C[(size_t)(r0 + 8) * N + c0] = v1;
        }
    }
}

// ---------------------------------------------------------------------------
// Tensor-core flash attention, split-bf16 (3-term), causal GQA.
// LPT scheduling: qb reversed so the heaviest q-blocks launch first.
// Loop-end __syncthreads() REQUIRED (round-8 race evidence).
// ---------------------------------------------------------------------------
#define AT_SMEM 196608

__global__ __launch_bounds__(256, 1) void attn_mma(
    const unsigned short* __restrict__ qh, const unsigned short* __restrict__ ql,
    const unsigned short* __restrict__ kh, const unsigned short* __restrict__ kl,
    const unsigned short* __restrict__ vh, const unsigned short* __restrict__ vl,
    unsigned short* __restrict__ oh, unsigned short* __restrict__ ol)
{
    extern __shared__ char smraw[];
    const uint32_t sb = smem_u32(smraw);
    const uint32_t QHs = sb;
    const uint32_t STs = sb + 65536;

    const int tid = threadIdx.x, wid = tid >> 5, lane = tid & 31;
    const int qb = (int)(gridDim.x - 1 - blockIdx.x);   // LPT: heavy first
    const int h = blockIdx.y, b = blockIdx.z;
    const int hk = h >> 2;
    const int qBase = qb * 128;
    const int nT = qb * 2 + 2;

    const unsigned short* Qhg = qh + ((size_t)(b * Hq + h) * Ts + qBase) * Dd;
    const unsigned short* Qlg = ql + ((size_t)(b * Hq + h) * Ts + qBase) * Dd;
    const unsigned short* Khg = kh + (size_t)(b * Hkv + hk) * Ts * Dd;
    const unsigned short* Klg = kl + (size_t)(b * Hkv + hk) * Ts * Dd;
    const unsigned short* Vhg = vh + (size_t)(b * Hkv + hk) * Dd * Ts;
    const unsigned short* Vlg = vl + (size_t)(b * Hkv + hk) * Dd * Ts;

    #pragma unroll
    for (int t = 0; t < 16; t++) {
        int idx = tid + t * 256;
        int arr = idx >> 11, rem = idx & 2047;
        int r = rem >> 4, c = rem & 15;
        uint32_t dst = QHs + arr * 32768 + r * 256 + ((c ^ (r & 7)) << 4);
        const unsigned short* s = (arr ? Qlg : Qhg) + (size_t)r * Dd + c * 8;
        CPA16(dst, s);
    }

    auto load_tile = [&](int st, int kt) {
        uint32_t base = STs + st * 65536;
        #pragma unroll
        for (int t = 0; t < 8; t++) {
            int idx = tid + t * 256;
            int arr = idx >> 10, rem = idx & 1023;
            int r = rem >> 4, c = rem & 15;
            uint32_t dst = base + arr * 16384 + r * 256 + ((c ^ (r & 7)) << 4);
            const unsigned short* s = (arr ? Klg : Khg) +
                (size_t)(kt * 64 + r) * Dd + c * 8;
            CPA16(dst, s);
        }
        #pragma unroll
        for (int t = 0; t < 8; t++) {
            int idx = tid + t * 256;
            int arr = idx >> 10, rem = idx & 1023;
            int r = rem >> 3, c = rem & 7;
            uint32_t dst = base + 32768 + arr * 16384 + r * 128 + ((c ^ (r & 7)) << 4);
            const unsigned short* s = (arr ? Vlg : Vhg) +
                (size_t)r * Ts + kt * 64 + c * 8;
            CPA16(dst, s);
        }
    };

    load_tile(0, 0);
    CPC();

    const int qrow = wid * 16 + (lane & 15);
    const uint32_t qpb = (uint32_t)(qrow * 256 + (((lane >> 4) ^ (qrow & 1)) << 4));
    const uint32_t qpx = (uint32_t)((qrow & 6) << 4);
    const int nIn = (lane & 7) + ((lane >> 4) << 3);
    const int cl  = (lane >> 3) & 1;

    float m0 = -INFINITY, m1 = -INFINITY, l0 = 0.0f, l1 = 0.0f;
    float O[16][4];
    #pragma unroll
    for (int i = 0; i < 16; i++)
        #pragma unroll
        for (int j = 0; j < 4; j++) O[i][j] = 0.0f;

    const int rA = qBase + wid * 16 + (lane >> 2);
    const int rB = rA + 8;

    for (int kt = 0; kt < nT; kt++) {
        if (kt + 1 < nT) { load_tile((kt + 1) & 1, kt + 1); CPC(); CPW(1); }
        else            { CPW(0); }
        __syncthreads();
        const uint32_t KB = STs + (kt & 1) * 65536;
        const uint32_t VB = KB + 32768;

        float S[8][4];
        #pragma unroll
        for (int i = 0; i < 8; i++)
            #pragma unroll
            for (int j = 0; j < 4; j++) S[i][j] = 0.0f;

        #pragma unroll
        for (int ks = 0; ks < 8; ks++) {
            uint32_t qa = QHs + qpb + (((uint32_t)ks << 5) ^ qpx);
            uint32_t ah[4], al[4];
            ldsm4(ah, qa);
            ldsm4(al, qa + 32768);
            #pragma unroll
            for (int np = 0; np < 4; np++) {
                int krow = np * 16 + nIn;
                uint32_t ka = KB + krow * 256 + ((uint32_t)((cl ^ (krow & 1)) << 4))
                            + (((uint32_t)ks << 5) ^ ((uint32_t)(krow & 6) << 4));
                uint32_t bh[4], bl[4];
                ldsm4(bh, ka);
                ldsm4(bl, ka + 16384);
                mma16816(S[2*np],   ah, &bh[0]);
                mma16816(S[2*np+1], ah, &bh[2]);
                mma16816(S[2*np],   ah, &bl[0]);
                mma16816(S[2*np+1], ah, &bl[2]);
                mma16816(S[2*np],   al, &bh[0]);
                mma16816(S[2*np+1], al, &bh[2]);
            }
        }

        if (kt >= 2 * qb) {
            #pragma unroll
            for (int nt = 0; nt < 8; nt++) {
                int jg = kt * 64 + nt * 8 + (lane & 3) * 2;
                S[nt][0] = (jg     <= rA) ? S[nt][0] * ATTN_SCALE : -30000.0f;
                S[nt][1] = (jg + 1 <= rA) ? S[nt][1] * ATTN_SCALE : -30000.0f;
                S[nt][2] = (jg     <= rB) ? S[nt][2] * ATTN_SCALE : -30000.0f;
                S[nt][3] = (jg + 1 <= rB) ? S[nt][3] * ATTN_SCALE : -30000.0f;
            }
        } else {
            #pragma unroll
            for (int nt = 0; nt < 8; nt++) {
                S[nt][0] *= ATTN_SCALE; S[nt][1] *= ATTN_SCALE;
                S[nt][2] *= ATTN_SCALE; S[nt][3] *= ATTN_SCALE;
            }
        }

        float bm0 = -INFINITY, bm1 = -INFINITY;
        #pragma unroll
        for (int nt = 0; nt < 8; nt++) {
            bm0 = fmaxf(bm0, fmaxf(S[nt][0], S[nt][1]));
            bm1 = fmaxf(bm1, fmaxf(S[nt][2], S[nt][3]));
        }
        bm0 = fmaxf(bm0, __shfl_xor_sync(0xffffffffu, bm0, 1));
        bm0 = fmaxf(bm0, __shfl_xor_sync(0xffffffffu, bm0, 2));
        bm1 = fmaxf(bm1, __shfl_xor_sync(0xffffffffu, bm1, 1));
        bm1 = fmaxf(bm1, __shfl_xor_sync(0xffffffffu, bm1, 2));
        float mn0 = fmaxf(m0, bm0);
        float mn1 = fmaxf(m1, bm1);

        float bs0 = 0.0f, bs1 = 0.0f;
        #pragma unroll
        for (int nt = 0; nt < 8; nt++) {
            S[nt][0] = __expf(S[nt][0] - mn0); bs0 += S[nt][0];
            S[nt][1] = __expf(S[nt][1] - mn0); bs0 += S[nt][1];
            S[nt][2] = __expf(S[nt][2] - mn1); bs1 += S[nt][2];
            S[nt][3] = __expf(S[nt][3] - mn1); bs1 += S[nt][3];
        }
        bs0 += __shfl_xor_sync(0xffffffffu, bs0, 1);
        bs0 += __shfl_xor_sync(0xffffffffu, bs0, 2);
        bs1 += __shfl_xor_sync(0xffffffffu, bs1, 1);
        bs1 += __shfl_xor_sync(0xffffffffu, bs1, 2);

        float a0 = __expf(m0 - mn0);
        float a1 = __expf(m1 - mn1);
        l0 = l0 * a0 + bs0;
        l1 = l1 * a1 + bs1;
        m0 = mn0; m1 = mn1;
        #pragma unroll
        for (int dt = 0; dt < 16; dt++) {
            O[dt][0] *= a0; O[dt][1] *= a0;
            O[dt][2] *= a1; O[dt][3] *= a1;
        }

        #pragma unroll
        for (int j = 0; j < 4; j++) {
            uint32_t pah[4], pal[4];
            pah[0] = pk2  (S[2*j][0],   S[2*j][1]);
            pah[1] = pk2  (S[2*j][2],   S[2*j][3]);
            pah[2] = pk2  (S[2*j+1][0], S[2*j+1][1]);
            pah[3] = pk2  (S[2*j+1][2], S[2*j+1][3]);
            pal[0] = pk2lo(S[2*j][0],   S[2*j][1]);
            pal[1] = pk2lo(S[2*j][2],   S[2*j][3]);
            pal[2] = pk2lo(S[2*j+1][0], S[2*j+1][1]);
            pal[3] = pk2lo(S[2*j+1][2], S[2*j+1][3]);
            #pragma unroll
            for (int dp = 0; dp < 8; dp++) {
                int vrow = dp * 16 + nIn;
                uint32_t va = VB + vrow * 128 + ((uint32_t)((cl ^ (vrow & 1)) << 4))
                            + (((uint32_t)j << 5) ^ ((uint32_t)(vrow & 6) << 4));
                uint32_t bh[4], bl[4];
                ldsm4(bh, va);
                ldsm4(bl, va + 16384);
                mma16816(O[2*dp],   pah, &bh[0]);
                mma16816(O[2*dp+1], pah, &bh[2]);
                mma16816(O[2*dp],   pah, &bl[0]);
                mma16816(O[2*dp+1], pah, &bl[2]);
                mma16816(O[2*dp],   pal, &bh[0]);
                mma16816(O[2*dp+1], pal, &bh[2]);
            }
        }
        __syncthreads();   // REQUIRED write-after-read guard
    }

    float inv0 = 1.0f / l0;
    float inv1 = 1.0f / l1;
    size_t rowA = ((size_t)(b * Ts + rA)) * INNER + h * Dd;
    size_t rowB = ((size_t)(b * Ts + rB)) * INNER + h * Dd;
    #pragma unroll
    for (int dt = 0; dt < 16; dt++) {
        int col = dt * 8 + (lane & 3) * 2;
        float x0 = O[dt][0] * inv0, x1 = O[dt][1] * inv0;
        float y0 = O[dt][2] * inv1, y1 = O[dt][3] * inv1;
        *(uint32_t*)&oh[rowA + col] = pk2(x0, x1);
        *(uint32_t*)&ol[rowA + col] = pk2lo(x0, x1);
        *(uint32_t*)&oh[rowB + col] = pk2(y0, y1);
        *(uint32_t*)&ol[rowB + col] = pk2lo(y0, y1);
    }
}

// ---------------------------------------------------------------------------
// Launch
// ---------------------------------------------------------------------------
extern "C" void kernel_launch(void* const* d_in, const int* in_sizes, int n_in,
                              void* d_out, int out_size)
{
    const float* stm  = (const float*)d_in[0];
    const float* wq   = (const float*)d_in[1];
    const float* wk   = (const float*)d_in[2];
    const float* wv   = (const float*)d_in[3];
    const float* wo   = (const float*)d_in[4];
    const float* cosv = (const float*)d_in[5];
    const float* sinv = (const float*)d_in[6];
    float* out = (float*)d_out;

    float* qkv;
    cudaGetSymbolAddress((void**)&qkv, g_qkv);
    unsigned short *xh, *xl, *wah, *wal, *woh, *wol, *oh, *ol;
    cudaGetSymbolAddress((void**)&xh,  g_xh);  cudaGetSymbolAddress((void**)&xl,  g_xl);
    cudaGetSymbolAddress((void**)&wah, g_wah); cudaGetSymbolAddress((void**)&wal, g_wal);
    cudaGetSymbolAddress((void**)&woh, g_woh); cudaGetSymbolAddress((void**)&wol, g_wol);
    cudaGetSymbolAddress((void**)&oh,  g_oh);  cudaGetSymbolAddress((void**)&ol,  g_ol);
    unsigned short *qh2, *ql2, *kh2, *kl2, *vth, *vtl;
    cudaGetSymbolAddress((void**)&qh2, g_qh2); cudaGetSymbolAddress((void**)&ql2, g_ql2);
    cudaGetSymbolAddress((void**)&kh2, g_kh2); cudaGetSymbolAddress((void**)&kl2, g_kl2);
    cudaGetSymbolAddress((void**)&vth, g_vth); cudaGetSymbolAddress((void**)&vtl, g_vtl);

    cudaFuncSetAttribute(gemm_mma, cudaFuncAttributeMaxDynamicSharedMemorySize, GSMEM);
    cudaFuncSetAttribute(attn_mma, cudaFuncAttributeMaxDynamicSharedMemorySize, AT_SMEM);

    const size_t wkOff = (size_t)INNER * INNER;          // rows [4096, 5120)
    const size_t wvOff = (size_t)(INNER + KVIN) * INNER; // rows [5120, 6144)

    // 1: split activations
    split_kernel<<<MTOT*INNER/1024, 256>>>(stm, xh, xl, MTOT*INNER);
    // 2-4: transpose+split wq/wk/wv into one concatenated [6144,4096] buffer
    transpose_split<<<dim3(INNER/32, INNER/32), dim3(32,8)>>>(wq, wah, wal, INNER, INNER);
    transpose_split<<<dim3(KVIN/32,  INNER/32), dim3(32,8)>>>(wk, wah + wkOff, wal + wkOff, INNER, KVIN);
    transpose_split<<<dim3(KVIN/32,  INNER/32), dim3(32,8)>>>(wv, wah + wvOff, wal + wvOff, INNER, KVIN);
    // 5: fused QKV projection (single gemm, N=6144, 1536 CTAs)
    gemm_mma<<<dim3(QKVN/128, MTOT/128), 256, GSMEM>>>(xh, xl, wah, wal, qkv, QKVN, INNER);
    // 6: wo transpose (needed only before final gemm)
    transpose_split<<<dim3(INNER/32, INNER/32), dim3(32,8)>>>(wo, woh, wol, INNER, INNER);
    // 7-8: fused RoPE + split + relayout (reads fused buffer)
    {
        int nq = Bb * Ts * Hq  * 64;
        int nk = Bb * Ts * Hkv * 64;
        rope_split<<<(nq + 255) / 256, 256>>>(qkv, cosv, sinv, qh2, ql2, Hq,  0,     nq);
        rope_split<<<(nk + 255) / 256, 256>>>(qkv, cosv, sinv, kh2, kl2, Hkv, INNER, nk);
    }
    // 9: V transpose+split (reads fused buffer)
    vtrans_split<<<dim3(Ts/32, Dd/32, Bb*Hkv), dim3(32,8)>>>(qkv, vth, vtl);
    // 10: attention
    attn_mma<<<dim3(Ts/128, Hq, Bb), 256, AT_SMEM>>>(qh2, ql2, kh2, kl2, vth, vtl, oh, ol);
    // 11: output projection
    gemm_mma<<<dim3(INNER/128, MTOT/128), 256, GSMEM>>>(oh, ol, woh, wol, out, INNER, INNER);
}

// round 11
// speedup vs baseline: 1.1385x; 1.0133x over previous
#include <cuda_runtime.h>
#include <cuda_bf16.h>
#include <math.h>
#include <stdint.h>

// Problem constants
#define Bb    2
#define Ts    2048
#define Hq    32
#define Hkv   8
#define Dd    128
#define INNER 4096
#define KVIN  1024
#define QKVN  6144              // 4096 (q) + 1024 (k) + 1024 (v)
#define MTOT  4096              // B*T
#define ATTN_SCALE 0.08838834764831845f

// ---------------------------------------------------------------------------
// Scratch (device globals)
// ---------------------------------------------------------------------------
// bf16 split-precision operands (raw u16)
__device__ unsigned short g_xh [MTOT*INNER],  g_xl [MTOT*INNER];
__device__ unsigned short g_wah[QKVN*INNER],  g_wal[QKVN*INNER];   // [wq;wk;wv]^T rows
__device__ unsigned short g_woh[INNER*INNER], g_wol[INNER*INNER];
__device__ unsigned short g_oh [MTOT*INNER],  g_ol [MTOT*INNER];

// attention operands (written directly by the fused QKV gemm epilogue)
__device__ unsigned short g_qh2[Bb*Hq*Ts*Dd],  g_ql2[Bb*Hq*Ts*Dd];    // [b,h,t,d]
__device__ unsigned short g_kh2[Bb*Hkv*Ts*Dd], g_kl2[Bb*Hkv*Ts*Dd];   // [b,hkv,t,d]
__device__ unsigned short g_vth[Bb*Hkv*Ts*Dd], g_vtl[Bb*Hkv*Ts*Dd];   // [b,hkv,d,t]

// ---------------------------------------------------------------------------
// Helpers
// ---------------------------------------------------------------------------
__device__ __forceinline__ uint32_t smem_u32(const void* p) {
    uint32_t a;
    asm("{ .reg .u64 t; cvta.to.shared.u64 t, %1; cvt.u32.u64 %0, t; }"
        : "=r"(a) : "l"(p));
    return a;
}
#define CPA16(d,s) asm volatile("cp.async.cg.shared.global [%0], [%1], 16;" :: "r"(d), "l"(s))
#define CPC()      asm volatile("cp.async.commit_group;" ::: "memory")
#define CPW(n)     asm volatile("cp.async.wait_group %0;" :: "n"(n) : "memory")

__device__ __forceinline__ void ldsm4(uint32_t* r, uint32_t a) {
    asm volatile("ldmatrix.sync.aligned.m8n8.x4.shared.b16 {%0,%1,%2,%3}, [%4];"
        : "=r"(r[0]), "=r"(r[1]), "=r"(r[2]), "=r"(r[3]) : "r"(a));
}
__device__ __forceinline__ void mma16816(float* c, const uint32_t* a, const uint32_t* b) {
    asm volatile("mma.sync.aligned.m16n8k16.row.col.f32.bf16.bf16.f32 "
        "{%0,%1,%2,%3}, {%4,%5,%6,%7}, {%8,%9}, {%0,%1,%2,%3};"
        : "+f"(c[0]), "+f"(c[1]), "+f"(c[2]), "+f"(c[3])
        : "r"(a[0]), "r"(a[1]), "r"(a[2]), "r"(a[3]), "r"(b[0]), "r"(b[1]));
}

__device__ __forceinline__ unsigned short f2bf(float x) {
    __nv_bfloat16 h = __float2bfloat16(x);
    return *reinterpret_cast<unsigned short*>(&h);
}
__device__ __forceinline__ float bf2f(unsigned short u) {
    __nv_bfloat16 h = *reinterpret_cast<__nv_bfloat16*>(&u);
    return __bfloat162float(h);
}
__device__ __forceinline__ uint32_t pk2(float a, float b) {
    return (uint32_t)f2bf(a) | ((uint32_t)f2bf(b) << 16);
}
__device__ __forceinline__ uint32_t pk2lo(float a, float b) {
    return pk2(a - bf2f(f2bf(a)), b - bf2f(f2bf(b)));
}

// ---------------------------------------------------------------------------
// Conversion kernels
// ---------------------------------------------------------------------------
__global__ void split_kernel(const float* __restrict__ x,
                             unsigned short* __restrict__ h,
                             unsigned short* __restrict__ l, int n)
{
    int i = (blockIdx.x * 256 + threadIdx.x) * 4;
    if (i >= n) return;
    float4 v = *(const float4*)(x + i);
    unsigned short h0 = f2bf(v.x), h1 = f2bf(v.y), h2 = f2bf(v.z), h3 = f2bf(v.w);
    ushort4 hh; hh.x = h0; hh.y = h1; hh.z = h2; hh.w = h3;
    *(ushort4*)(h + i) = hh;
    ushort4 ll;
    ll.x = f2bf(v.x - bf2f(h0)); ll.y = f2bf(v.y - bf2f(h1));
    ll.z = f2bf(v.z - bf2f(h2)); ll.w = f2bf(v.w - bf2f(h3));
    *(ushort4*)(l + i) = ll;
}

// w[K,N] -> out[N,K] (transpose) + hi/lo split
__global__ void transpose_split(const float* __restrict__ w,
                                unsigned short* __restrict__ th,
                                unsigned short* __restrict__ tl, int K, int N)
{
    __shared__ float t[32][33];
    int n0 = blockIdx.x * 32, k0 = blockIdx.y * 32;
    #pragma unroll
    for (int i = 0; i < 32; i += 8)
        t[threadIdx.y + i][threadIdx.x] =
            w[(size_t)(k0 + threadIdx.y + i) * N + n0 + threadIdx.x];
    __syncthreads();
    #pragma unroll
    for (int i = 0; i < 32; i += 8) {
        float x = t[threadIdx.x][threadIdx.y + i];
        size_t o = (size_t)(n0 + threadIdx.y + i) * K + k0 + threadIdx.x;
        unsigned short hb = f2bf(x);
        th[o] = hb;
        tl[o] = f2bf(x - bf2f(hb));
    }
}

// ---------------------------------------------------------------------------
// Shared GEMM mainloop (macro-free device inline): computes the 128x128 tile
// accumulators. CTA 128x128, 8 warps (64m x 32n), K chunk 32, 3-stage
// cp.async, ONE barrier per chunk (verified safe in rounds 8-9).
// ---------------------------------------------------------------------------
#define NSTG  3
#define STGB  32768
#define GSMEM (NSTG*STGB)

__device__ __forceinline__ void gemm_mainloop(
    const unsigned short* __restrict__ Ah, const unsigned short* __restrict__ Al,
    const unsigned short* __restrict__ Bh, const unsigned short* __restrict__ Bl,
    int K, int mBase, int nBase, uint32_t sb, float cacc[4][4][4])
{
    const int tid  = threadIdx.x;
    const int wid  = tid >> 5;
    const int lane = tid & 31;
    const int warp_m = (wid & 1) * 64;
    const int warp_n = (wid >> 1) * 32;

    uint32_t aAddr[4], bAddr[2];
    {
        int r    = lane & 15;
        int half = lane >> 4;
        #pragma unroll
        for (int mt = 0; mt < 4; mt++) {
            int row = warp_m + mt * 16 + r;
            int sw  = (row >> 1) & 3;
            aAddr[mt] = sb + row * 64 + ((half ^ sw) << 4);
        }
        int nIn = (lane & 7) + (lane >> 4) * 8;
        int cl  = (lane >> 3) & 1;
        #pragma unroll
        for (int bt = 0; bt < 2; bt++) {
            int row = warp_n + bt * 16 + nIn;
            int sw  = (row >> 1) & 3;
            bAddr[bt] = sb + 16384 + row * 64 + ((cl ^ sw) << 4);
        }
    }

    const int ldRow = tid >> 2;
    const int ldC   = tid & 3;

    #pragma unroll
    for (int a = 0; a < 4; a++)
        #pragma unroll
        for (int b = 0; b < 4; b++)
            #pragma unroll
            for (int c = 0; c < 4; c++) cacc[a][b][c] = 0.0f;

    const int NCH = K >> 5;

    auto load_chunk = [&](int st, int k0) {
        #pragma unroll
        for (int h = 0; h < 2; h++) {
            int row = ldRow + h * 64;
            int sw  = (row >> 1) & 3;
            uint32_t so = sb + st * STGB + row * 64 + ((ldC ^ sw) << 4);
            size_t ga = (size_t)(mBase + row) * K + k0 + ldC * 8;
            CPA16(so,         Ah + ga);
            CPA16(so + 8192,  Al + ga);
            size_t gb = (size_t)(nBase + row) * K + k0 + ldC * 8;
            CPA16(so + 16384, Bh + gb);
            CPA16(so + 24576, Bl + gb);
        }
        CPC();
    };

    load_chunk(0, 0);
    load_chunk(1, 32);

    int st = 0, ldst = 2;
    for (int i = 0; i < NCH; i++) {
        CPW(1);
        __syncthreads();
        int nx = i + 2;
        if (nx < NCH) load_chunk(ldst, nx << 5);
        else          CPC();

        uint32_t stOff = (uint32_t)st * STGB;
        #pragma unroll
        for (int s = 0; s < 2; s++) {
            uint32_t sx = (uint32_t)(s << 5);
            uint32_t a_hi[4][4], a_lo[4][4];
            #pragma unroll
            for (int mt = 0; mt < 4; mt++) {
                uint32_t ad = (aAddr[mt] ^ sx) + stOff;
                ldsm4(a_hi[mt], ad);
                ldsm4(a_lo[mt], ad + 8192);
            }
            #pragma unroll
            for (int bt = 0; bt < 2; bt++) {
                uint32_t bd = (bAddr[bt] ^ sx) + stOff;
                uint32_t b_hi[4], b_lo[4];
                ldsm4(b_hi, bd);
                ldsm4(b_lo, bd + 8192);
                #pragma unroll
                for (int mt = 0; mt < 4; mt++) {
                    mma16816(cacc[mt][bt*2],   a_hi[mt], &b_hi[0]);
                    mma16816(cacc[mt][bt*2+1], a_hi[mt], &b_hi[2]);
                    mma16816(cacc[mt][bt*2],   a_hi[mt], &b_lo[0]);
                    mma16816(cacc[mt][bt*2+1], a_hi[mt], &b_lo[2]);
                    mma16816(cacc[mt][bt*2],   a_lo[mt], &b_hi[0]);
                    mma16816(cacc[mt][bt*2+1], a_lo[mt], &b_hi[2]);
                }
            }
        }
        if (++st   == NSTG) st   = 0;
        if (++ldst == NSTG) ldst = 0;
    }
}

// Plain GEMM (wo projection): fp32 store
__global__ __launch_bounds__(256, 2) void gemm_mma(
    const unsigned short* __restrict__ Ah, const unsigned short* __restrict__ Al,
    const unsigned short* __restrict__ Bh, const unsigned short* __restrict__ Bl,
    float* __restrict__ C, int N, int K)
{
    extern __shared__ char smraw[];
    const uint32_t sb = smem_u32(smraw);
    const int mBase = blockIdx.y * 128;
    const int nBase = blockIdx.x * 128;
    float cacc[4][4][4];
    gemm_mainloop(Ah, Al, Bh, Bl, K, mBase, nBase, sb, cacc);

    const int wid  = threadIdx.x >> 5;
    const int lane = threadIdx.x & 31;
    const int rBase = mBase + (wid & 1) * 64 + (lane >> 2);
    const int cBase = nBase + (wid >> 1) * 32 + (lane & 3) * 2;
    #pragma unroll
    for (int mt = 0; mt < 4; mt++) {
        #pragma unroll
        for (int nt = 0; nt < 4; nt++) {
            int r0 = rBase + mt * 16;
            int c0 = cBase + nt * 8;
            float2 v0 = make_float2(cacc[mt][nt][0], cacc[mt][nt][1]);
            float2 v1 = make_float2(cacc[mt][nt][2], cacc[mt][nt][3]);
            *(float2*)&C[(size_t)r0 * N + c0]       = v0;
            *(float2*)&C[(size_t)(r0 + 8) * N + c0] = v1;
        }
    }
}

// Fused QKV GEMM: mainloop + per-head epilogue (RoPE+split for Q/K heads,
// transpose+split for V heads). Each N-tile (128 cols) == one head.
// Numerics identical to the old g_qkv -> rope_split / vtrans_split path.
__global__ __launch_bounds__(256, 2) void gemm_qkv(
    const unsigned short* __restrict__ Ah, const unsigned short* __restrict__ Al,
    const unsigned short* __restrict__ Bh, const unsigned short* __restrict__ Bl,
    const float* __restrict__ cs, const float* __restrict__ sn,
    unsigned short* __restrict__ qh, unsigned short* __restrict__ ql,
    unsigned short* __restrict__ kh, unsigned short* __restrict__ kl,
    unsigned short* __restrict__ vh, unsigned short* __restrict__ vl)
{
    extern __shared__ char smraw[];
    const uint32_t sb = smem_u32(smraw);
    const int tid   = threadIdx.x;
    const int mBase = blockIdx.y * 128;
    const int nBase = blockIdx.x * 128;
    float cacc[4][4][4];
    gemm_mainloop(Ah, Al, Bh, Bl, INNER, mBase, nBase, sb, cacc);

    // Stage accumulator tile to smem (stride 129 floats: conflict-free for
    // both row-wise and column-strided reads). 128*129*4 = 66048 B <= 96 KB.
    __syncthreads();   // all warps done with pipeline smem reads
    float* sm = (float*)smraw;
    {
        const int wid  = tid >> 5;
        const int lane = tid & 31;
        const int rB = (wid & 1) * 64 + (lane >> 2);
        const int cB = (wid >> 1) * 32 + (lane & 3) * 2;
        #pragma unroll
        for (int mt = 0; mt < 4; mt++) {
            #pragma unroll
            for (int nt = 0; nt < 4; nt++) {
                int r0 = rB + mt * 16;
                int c0 = cB + nt * 8;
                sm[r0 * 129 + c0]           = cacc[mt][nt][0];
                sm[r0 * 129 + c0 + 1]       = cacc[mt][nt][1];
                sm[(r0 + 8) * 129 + c0]     = cacc[mt][nt][2];
                sm[(r0 + 8) * 129 + c0 + 1] = cacc[mt][nt][3];
            }
        }
    }
    __syncthreads();

    if (nBase < INNER + KVIN) {
        // ---- Q or K head: RoPE + hi/lo split -> [b,HH,t,d] ----
        int HH, hd;
        unsigned short *dh, *dl;
        if (nBase < INNER) { HH = Hq;  hd = nBase >> 7;           dh = qh; dl = ql; }
        else               { HH = Hkv; hd = (nBase - INNER) >> 7; dh = kh; dl = kl; }
        for (int p = tid; p < 128 * 64; p += 256) {
            int r = p >> 6, d = p & 63;
            int bt = mBase + r;
            int t = bt & (Ts - 1), b = bt >> 11;
            float l  = sm[r * 129 + d];
            float rr = sm[r * 129 + d + 64];
            float c0 = cs[t * 128 + d],      s0 = sn[t * 128 + d];
            float c1 = cs[t * 128 + d + 64], s1 = sn[t * 128 + d + 64];
            float f0 = l * c0 - rr * s0;
            float f1 = rr * c1 + l * s1;
            size_t ob = ((size_t)((b * HH + hd) * Ts + t)) << 7;
            unsigned short h0 = f2bf(f0);
            dh[ob + d] = h0;
            dl[ob + d] = f2bf(f0 - bf2f(h0));
            unsigned short h1 = f2bf(f1);
            dh[ob + d + 64] = h1;
            dl[ob + d + 64] = f2bf(f1 - bf2f(h1));
        }
    } else {
        // ---- V head: transpose + hi/lo split -> [b,hkv,d,t] ----
        int hk = (nBase - INNER - KVIN) >> 7;
        int tl_ = tid & 127;
        int bt = mBase + tl_;
        int t = bt & (Ts - 1), b = bt >> 11;
        for (int d = (tid >> 7); d < 128; d += 2) {
            float x = sm[tl_ * 129 + d];
            size_t o = ((size_t)((b * Hkv + hk) * Dd + d)) * Ts + t;
            unsigned short hb = f2bf(x);
            vh[o] = hb;
            vl[o] = f2bf(x - bf2f(hb));
        }
    }
}

// ---------------------------------------------------------------------------
// Tensor-core flash attention, split-bf16 (3-term), causal GQA.
// LPT scheduling; loop-end __syncthreads() REQUIRED (round-8 race evidence).
// ---------------------------------------------------------------------------
#define AT_SMEM 196608

__global__ __launch_bounds__(256, 1) void attn_mma(
    const unsigned short* __restrict__ qh, const unsigned short* __restrict__ ql,
    const unsigned short* __restrict__ kh, const unsigned short* __restrict__ kl,
    const unsigned short* __restrict__ vh, const unsigned short* __restrict__ vl,
    unsigned short* __restrict__ oh, unsigned short* __restrict__ ol)
{
    extern __shared__ char smraw[];
    const uint32_t sb = smem_u32(smraw);
    const uint32_t QHs = sb;
    const uint32_t STs = sb + 65536;

    const int tid = threadIdx.x, wid = tid >> 5, lane = tid & 31;
    const int qb = (int)(gridDim.x - 1 - blockIdx.x);   // LPT: heavy first
    const int h = blockIdx.y, b = blockIdx.z;
    const int hk = h >> 2;
    const int qBase = qb * 128;
    const int nT = qb * 2 + 2;

    const unsigned short* Qhg = qh + ((size_t)(b * Hq + h) * Ts + qBase) * Dd;
    const unsigned short* Qlg = ql + ((size_t)(b * Hq + h) * Ts + qBase) * Dd;
    const unsigned short* Khg = kh + (size_t)(b * Hkv + hk) * Ts * Dd;
    const unsigned short* Klg = kl + (size_t)(b * Hkv + hk) * Ts * Dd;
    const unsigned short* Vhg = vh + (size_t)(b * Hkv + hk) * Dd * Ts;
    const unsigned short* Vlg = vl + (size_t)(b * Hkv + hk) * Dd * Ts;

    #pragma unroll
    for (int t = 0; t < 16; t++) {
        int idx = tid + t * 256;
        int arr = idx >> 11, rem = idx & 2047;
        int r = rem >> 4, c = rem & 15;
        uint32_t dst = QHs + arr * 32768 + r * 256 + ((c ^ (r & 7)) << 4);
        const unsigned short* s = (arr ? Qlg : Qhg) + (size_t)r * Dd + c * 8;
        CPA16(dst, s);
    }

    auto load_tile = [&](int st, int kt) {
        uint32_t base = STs + st * 65536;
        #pragma unroll
        for (int t = 0; t < 8; t++) {
            int idx = tid + t * 256;
            int arr = idx >> 10, rem = idx & 1023;
            int r = rem >> 4, c = rem & 15;
            uint32_t dst = base + arr * 16384 + r * 256 + ((c ^ (r & 7)) << 4);
            const unsigned short* s = (arr ? Klg : Khg) +
                (size_t)(kt * 64 + r) * Dd + c * 8;
            CPA16(dst, s);
        }
        #pragma unroll
        for (int t = 0; t < 8; t++) {
            int idx = tid + t * 256;
            int arr = idx >> 10, rem = idx & 1023;
            int r = rem >> 3, c = rem & 7;
            uint32_t dst = base + 32768 + arr * 16384 + r * 128 + ((c ^ (r & 7)) << 4);
            const unsigned short* s = (arr ? Vlg : Vhg) +
                (size_t)r * Ts + kt * 64 + c * 8;
            CPA16(dst, s);
        }
    };

    load_tile(0, 0);
    CPC();

    const int qrow = wid * 16 + (lane & 15);
    const uint32_t qpb = (uint32_t)(qrow * 256 + (((lane >> 4) ^ (qrow & 1)) << 4));
    const uint32_t qpx = (uint32_t)((qrow & 6) << 4);
    const int nIn = (lane & 7) + ((lane >> 4) << 3);
    const int cl  = (lane >> 3) & 1;

    float m0 = -INFINITY, m1 = -INFINITY, l0 = 0.0f, l1 = 0.0f;
    float O[16][4];
    #pragma unroll
    for (int i = 0; i < 16; i++)
        #pragma unroll
        for (int j = 0; j < 4; j++) O[i][j] = 0.0f;

    const int rA = qBase + wid * 16 + (lane >> 2);
    const int rB = rA + 8;

    for (int kt = 0; kt < nT; kt++) {
        if (kt + 1 < nT) { load_tile((kt + 1) & 1, kt + 1); CPC(); CPW(1); }
        else            { CPW(0); }
        __syncthreads();
        const uint32_t KB = STs + (kt & 1) * 65536;
        const uint32_t VB = KB + 32768;

        float S[8][4];
        #pragma unroll
        for (int i = 0; i < 8; i++)
            #pragma unroll
            for (int j = 0; j < 4; j++) S[i][j] = 0.0f;

        #pragma unroll
        for (int ks = 0; ks < 8; ks++) {
            uint32_t qa = QHs + qpb + (((uint32_t)ks << 5) ^ qpx);
            uint32_t ah[4], al[4];
            ldsm4(ah, qa);
            ldsm4(al, qa + 32768);
            #pragma unroll
            for (int np = 0; np < 4; np++) {
                int krow = np * 16 + nIn;
                uint32_t ka = KB + krow * 256 + ((uint32_t)((cl ^ (krow & 1)) << 4))
                            + (((uint32_t)ks << 5) ^ ((uint32_t)(krow & 6) << 4));
                uint32_t bh[4], bl[4];
                ldsm4(bh, ka);
                ldsm4(bl, ka + 16384);
                mma16816(S[2*np],   ah, &bh[0]);
                mma16816(S[2*np+1], ah, &bh[2]);
                mma16816(S[2*np],   ah, &bl[0]);
                mma16816(S[2*np+1], ah, &bl[2]);
                mma16816(S[2*np],   al, &bh[0]);
                mma16816(S[2*np+1], al, &bh[2]);
            }
        }

        if (kt >= 2 * qb) {
            #pragma unroll
            for (int nt = 0; nt < 8; nt++) {
                int jg = kt * 64 + nt * 8 + (lane & 3) * 2;
                S[nt][0] = (jg     <= rA) ? S[nt][0] * ATTN_SCALE : -30000.0f;
                S[nt][1] = (jg + 1 <= rA) ? S[nt][1] * ATTN_SCALE : -30000.0f;
                S[nt][2] = (jg     <= rB) ? S[nt][2] * ATTN_SCALE : -30000.0f;
                S[nt][3] = (jg + 1 <= rB) ? S[nt][3] * ATTN_SCALE : -30000.0f;
            }
        } else {
            #pragma unroll
            for (int nt = 0; nt < 8; nt++) {
                S[nt][0] *= ATTN_SCALE; S[nt][1] *= ATTN_SCALE;
                S[nt][2] *= ATTN_SCALE; S[nt][3] *= ATTN_SCALE;
            }
        }

        float bm0 = -INFINITY, bm1 = -INFINITY;
        #pragma unroll
        for (int nt = 0; nt < 8; nt++) {
            bm0 = fmaxf(bm0, fmaxf(S[nt][0], S[nt][1]));
            bm1 = fmaxf(bm1, fmaxf(S[nt][2], S[nt][3]));
        }
        bm0 = fmaxf(bm0, __shfl_xor_sync(0xffffffffu, bm0, 1));
        bm0 = fmaxf(bm0, __shfl_xor_sync(0xffffffffu, bm0, 2));
        bm1 = fmaxf(bm1, __shfl_xor_sync(0xffffffffu, bm1, 1));
        bm1 = fmaxf(bm1, __shfl_xor_sync(0xffffffffu, bm1, 2));
        float mn0 = fmaxf(m0, bm0);
        float mn1 = fmaxf(m1, bm1);

        float bs0 = 0.0f, bs1 = 0.0f;
        #pragma unroll
        for (int nt = 0; nt < 8; nt++) {
            S[nt][0] = __expf(S[nt][0] - mn0); bs0 += S[nt][0];
            S[nt][1] = __expf(S[nt][1] - mn0); bs0 += S[nt][1];
            S[nt][2] = __expf(S[nt][2] - mn1); bs1 += S[nt][2];
            S[nt][3] = __expf(S[nt][3] - mn1); bs1 += S[nt][3];
        }
        bs0 += __shfl_xor_sync(0xffffffffu, bs0, 1);
        bs0 += __shfl_xor_sync(0xffffffffu, bs0, 2);
        bs1 += __shfl_xor_sync(0xffffffffu, bs1, 1);
        bs1 += __shfl_xor_sync(0xffffffffu, bs1, 2);

        float a0 = __expf(m0 - mn0);
        float a1 = __expf(m1 - mn1);
        l0 = l0 * a0 + bs0;
        l1 = l1 * a1 + bs1;
        m0 = mn0; m1 = mn1;
        #pragma unroll
        for (int dt = 0; dt < 16; dt++) {
            O[dt][0] *= a0; O[dt][1] *= a0;
            O[dt][2] *= a1; O[dt][3] *= a1;
        }

        #pragma unroll
        for (int j = 0; j < 4; j++) {
            uint32_t pah[4], pal[4];
            pah[0] = pk2  (S[2*j][0],   S[2*j][1]);
            pah[1] = pk2  (S[2*j][2],   S[2*j][3]);
            pah[2] = pk2  (S[2*j+1][0], S[2*j+1][1]);
            pah[3] = pk2  (S[2*j+1][2], S[2*j+1][3]);
            pal[0] = pk2lo(S[2*j][0],   S[2*j][1]);
            pal[1] = pk2lo(S[2*j][2],   S[2*j][3]);
            pal[2] = pk2lo(S[2*j+1][0], S[2*j+1][1]);
            pal[3] = pk2lo(S[2*j+1][2], S[2*j+1][3]);
            #pragma unroll
            for (int dp = 0; dp < 8; dp++) {
                int vrow = dp * 16 + nIn;
                uint32_t va = VB + vrow * 128 + ((uint32_t)((cl ^ (vrow & 1)) << 4))
                            + (((uint32_t)j << 5) ^ ((uint32_t)(vrow & 6) << 4));
                uint32_t bh[4], bl[4];
                ldsm4(bh, va);
                ldsm4(bl, va + 16384);
                mma16816(O[2*dp],   pah, &bh[0]);
                mma16816(O[2*dp+1], pah, &bh[2]);
                mma16816(O[2*dp],   pah, &bl[0]);
                mma16816(O[2*dp+1], pah, &bl[2]);
                mma16816(O[2*dp],   pal, &bh[0]);
                mma16816(O[2*dp+1], pal, &bh[2]);
            }
        }
        __syncthreads();   // REQUIRED write-after-read guard
    }

    float inv0 = 1.0f / l0;
    float inv1 = 1.0f / l1;
    size_t rowA = ((size_t)(b * Ts + rA)) * INNER + h * Dd;
    size_t rowB = ((size_t)(b * Ts + rB)) * INNER + h * Dd;
    #pragma unroll
    for (int dt = 0; dt < 16; dt++) {
        int col = dt * 8 + (lane & 3) * 2;
        float x0 = O[dt][0] * inv0, x1 = O[dt][1] * inv0;
        float y0 = O[dt][2] * inv1, y1 = O[dt][3] * inv1;
        *(uint32_t*)&oh[rowA + col] = pk2(x0, x1);
        *(uint32_t*)&ol[rowA + col] = pk2lo(x0, x1);
        *(uint32_t*)&oh[rowB + col] = pk2(y0, y1);
        *(uint32_t*)&ol[rowB + col] = pk2lo(y0, y1);
    }
}

// ---------------------------------------------------------------------------
// Launch
// ---------------------------------------------------------------------------
extern "C" void kernel_launch(void* const* d_in, const int* in_sizes, int n_in,
                              void* d_out, int out_size)
{
    const float* stm  = (const float*)d_in[0];
    const float* wq   = (const float*)d_in[1];
    const float* wk   = (const float*)d_in[2];
    const float* wv   = (const float*)d_in[3];
    const float* wo   = (const float*)d_in[4];
    const float* cosv = (const float*)d_in[5];
    const float* sinv = (const float*)d_in[6];
    float* out = (float*)d_out;

    unsigned short *xh, *xl, *wah, *wal, *woh, *wol, *oh, *ol;
    cudaGetSymbolAddress((void**)&xh,  g_xh);  cudaGetSymbolAddress((void**)&xl,  g_xl);
    cudaGetSymbolAddress((void**)&wah, g_wah); cudaGetSymbolAddress((void**)&wal, g_wal);
    cudaGetSymbolAddress((void**)&woh, g_woh); cudaGetSymbolAddress((void**)&wol, g_wol);
    cudaGetSymbolAddress((void**)&oh,  g_oh);  cudaGetSymbolAddress((void**)&ol,  g_ol);
    unsigned short *qh2, *ql2, *kh2, *kl2, *vth, *vtl;
    cudaGetSymbolAddress((void**)&qh2, g_qh2); cudaGetSymbolAddress((void**)&ql2, g_ql2);
    cudaGetSymbolAddress((void**)&kh2, g_kh2); cudaGetSymbolAddress((void**)&kl2, g_kl2);
    cudaGetSymbolAddress((void**)&vth, g_vth); cudaGetSymbolAddress((void**)&vtl, g_vtl);

    cudaFuncSetAttribute(gemm_mma, cudaFuncAttributeMaxDynamicSharedMemorySize, GSMEM);
    cudaFuncSetAttribute(gemm_qkv, cudaFuncAttributeMaxDynamicSharedMemorySize, GSMEM);
    cudaFuncSetAttribute(attn_mma, cudaFuncAttributeMaxDynamicSharedMemorySize, AT_SMEM);

    const size_t wkOff = (size_t)INNER * INNER;          // rows [4096, 5120)
    const size_t wvOff = (size_t)(INNER + KVIN) * INNER; // rows [5120, 6144)

    // 1: split activations
    split_kernel<<<MTOT*INNER/1024, 256>>>(stm, xh, xl, MTOT*INNER);
    // 2-4: transpose+split wq/wk/wv into one concatenated [6144,4096] buffer
    transpose_split<<<dim3(INNER/32, INNER/32), dim3(32,8)>>>(wq, wah, wal, INNER, INNER);
    transpose_split<<<dim3(KVIN/32,  INNER/32), dim3(32,8)>>>(wk, wah + wkOff, wal + wkOff, INNER, KVIN);
    transpose_split<<<dim3(KVIN/32,  INNER/32), dim3(32,8)>>>(wv, wah + wvOff, wal + wvOff, INNER, KVIN);
    // 5: fused QKV projection + RoPE/split/transpose epilogue
    gemm_qkv<<<dim3(QKVN/128, MTOT/128), 256, GSMEM>>>(
        xh, xl, wah, wal, cosv, sinv, qh2, ql2, kh2, kl2, vth, vtl);
    // 6: wo transpose (needed only before final gemm)
    transpose_split<<<dim3(INNER/32, INNER/32), dim3(32,8)>>>(wo, woh, wol, INNER, INNER);
    // 7: attention
    attn_mma<<<dim3(Ts/128, Hq, Bb), 256, AT_SMEM>>>(qh2, ql2, kh2, kl2, vth, vtl, oh, ol);
    // 8: output projection
    gemm_mma<<<dim3(INNER/128, MTOT/128), 256, GSMEM>>>(oh, ol, woh, wol, out, INNER, INNER);
}